// round 2
// baseline (speedup 1.0000x reference)
#include <cuda_runtime.h>
#include <cuda_bf16.h>

// Problem constants
#define BB   128
#define TT   256
#define CC   384
#define HH   6
#define HS   64
#define MTOT (BB*TT)          // 32768 rows
#define QKVN (3*HH*HS)        // 1152

// Scratch in device globals (allocation-free rule)
__device__ float g_q[BB*HH*TT*HS];     // [b,h,t,d]
__device__ float g_k[BB*HH*TT*HS];
__device__ float g_v[BB*HH*TT*HS];
__device__ float g_att[MTOT*CC];       // [b,t, h*64+d] concat layout

// ---------------------------------------------------------------------------
// Kernel 1: fused QKV projection.
// Grid: (512, 18). Each block: 64 rows (m) x 64 cols, where blockIdx.y picks
// (tensor, head) — each head is exactly one 64-wide N tile.
// ---------------------------------------------------------------------------
__global__ __launch_bounds__(256) void qkv_kernel(
    const float* __restrict__ x,
    const float* __restrict__ Wq,
    const float* __restrict__ Wk,
    const float* __restrict__ Wv)
{
    __shared__ float As[16][68];   // padded, [k][m]
    __shared__ float Bs[16][64];   // [k][d]

    const int m0 = blockIdx.x * 64;
    const int nt = blockIdx.y;                  // 0..17
    const int tensor = nt / HH;
    const int h      = nt % HH;
    const float* W = (tensor == 0 ? Wq : tensor == 1 ? Wk : Wv) + (size_t)h * CC * HS;
    float* out = (tensor == 0 ? g_q : tensor == 1 ? g_k : g_v);

    const int tid = threadIdx.x;
    const int ty = tid / 16, tx = tid % 16;     // compute coords
    const int arow = tid / 4, akv = (tid % 4) * 4;  // A-load coords
    const int bk = tid / 16, bd = (tid % 16) * 4;   // B-load coords

    float acc[4][4] = {};

    for (int k0 = 0; k0 < CC; k0 += 16) {
        __syncthreads();
        // A tile: 64 rows x 16 k, loaded as float4 along k, stored transposed
        float4 av = *(const float4*)&x[(size_t)(m0 + arow) * CC + k0 + akv];
        As[akv + 0][arow] = av.x;
        As[akv + 1][arow] = av.y;
        As[akv + 2][arow] = av.z;
        As[akv + 3][arow] = av.w;
        // B tile: 16 k x 64 d, contiguous in d
        *(float4*)&Bs[bk][bd] = *(const float4*)&W[(size_t)(k0 + bk) * HS + bd];
        __syncthreads();

        #pragma unroll
        for (int kk = 0; kk < 16; kk++) {
            float4 a = *(const float4*)&As[kk][ty * 4];
            float4 b = *(const float4*)&Bs[kk][tx * 4];
            float ar[4] = {a.x, a.y, a.z, a.w};
            float br[4] = {b.x, b.y, b.z, b.w};
            #pragma unroll
            for (int i = 0; i < 4; i++)
                #pragma unroll
                for (int j = 0; j < 4; j++)
                    acc[i][j] += ar[i] * br[j];
        }
    }

    // write out as [b,h,t,d]
    #pragma unroll
    for (int i = 0; i < 4; i++) {
        int m = m0 + ty * 4 + i;
        int b = m >> 8, t = m & 255;
        float4 r = {acc[i][0], acc[i][1], acc[i][2], acc[i][3]};
        *(float4*)&out[(((size_t)(b * HH + h) * TT + t) * HS) + tx * 4] = r;
    }
}

// ---------------------------------------------------------------------------
// Kernel 2: causal attention, flash-style in fp32.
// One block per (b,h); thread t owns query row t. K/V tiles of 64 rows in
// smem, online softmax over 16-key chunks.
// ---------------------------------------------------------------------------
__global__ __launch_bounds__(256) void attn_kernel()
{
    const int bh = blockIdx.x;            // 0..767
    const int b = bh / HH, h = bh % HH;
    const int t = threadIdx.x;            // query row

    const float* qb = g_q + (size_t)bh * TT * HS;
    const float* kb = g_k + (size_t)bh * TT * HS;
    const float* vb = g_v + (size_t)bh * TT * HS;

    __shared__ float Ks[64][64];
    __shared__ float Vs[64][64];

    float qr[64];
    #pragma unroll
    for (int d4 = 0; d4 < 16; d4++) {
        float4 qq = *(const float4*)&qb[(size_t)t * HS + d4 * 4];
        qr[d4 * 4 + 0] = qq.x * 0.125f;   // scale = 1/sqrt(64)
        qr[d4 * 4 + 1] = qq.y * 0.125f;
        qr[d4 * 4 + 2] = qq.z * 0.125f;
        qr[d4 * 4 + 3] = qq.w * 0.125f;
    }

    float o[64];
    #pragma unroll
    for (int d = 0; d < 64; d++) o[d] = 0.f;
    float mmax = -1e30f, l = 0.f;

    for (int j0 = 0; j0 < TT; j0 += 64) {
        __syncthreads();
        {
            int r  = threadIdx.x / 4;
            int cv = (threadIdx.x % 4) * 16;
            #pragma unroll
            for (int u = 0; u < 4; u++) {
                *(float4*)&Ks[r][cv + u * 4] = *(const float4*)&kb[(size_t)(j0 + r) * HS + cv + u * 4];
                *(float4*)&Vs[r][cv + u * 4] = *(const float4*)&vb[(size_t)(j0 + r) * HS + cv + u * 4];
            }
        }
        __syncthreads();

        if (t >= j0) {
            #pragma unroll
            for (int cc = 0; cc < 4; cc++) {
                const int sbase = j0 + cc * 16;
                if (sbase <= t) {
                    float sc[16];
                    #pragma unroll
                    for (int i = 0; i < 16; i++) {
                        float acc = 0.f;
                        const float4* kr = (const float4*)&Ks[cc * 16 + i][0];
                        #pragma unroll
                        for (int d4 = 0; d4 < 16; d4++) {
                            float4 kk = kr[d4];
                            acc += qr[d4 * 4 + 0] * kk.x + qr[d4 * 4 + 1] * kk.y
                                 + qr[d4 * 4 + 2] * kk.z + qr[d4 * 4 + 3] * kk.w;
                        }
                        sc[i] = (sbase + i <= t) ? acc : -1e30f;
                    }
                    float mnew = mmax;
                    #pragma unroll
                    for (int i = 0; i < 16; i++) mnew = fmaxf(mnew, sc[i]);
                    float corr = __expf(mmax - mnew);
                    mmax = mnew;
                    float psum = 0.f;
                    #pragma unroll
                    for (int i = 0; i < 16; i++) { sc[i] = __expf(sc[i] - mnew); psum += sc[i]; }
                    l = l * corr + psum;
                    #pragma unroll
                    for (int d = 0; d < 64; d++) o[d] *= corr;
                    #pragma unroll
                    for (int i = 0; i < 16; i++) {
                        const float4* vr = (const float4*)&Vs[cc * 16 + i][0];
                        float p = sc[i];
                        #pragma unroll
                        for (int d4 = 0; d4 < 16; d4++) {
                            float4 vv = vr[d4];
                            o[d4 * 4 + 0] += p * vv.x;
                            o[d4 * 4 + 1] += p * vv.y;
                            o[d4 * 4 + 2] += p * vv.z;
                            o[d4 * 4 + 3] += p * vv.w;
                        }
                    }
                }
            }
        }
    }

    const float inv = 1.f / l;
    float* op = g_att + ((size_t)(b * TT + t)) * CC + h * HS;
    #pragma unroll
    for (int d4 = 0; d4 < 16; d4++) {
        float4 r;
        r.x = o[d4 * 4 + 0] * inv;
        r.y = o[d4 * 4 + 1] * inv;
        r.z = o[d4 * 4 + 2] * inv;
        r.w = o[d4 * 4 + 3] * inv;
        *(float4*)&op[d4 * 4] = r;
    }
}

// ---------------------------------------------------------------------------
// Kernel 3: output projection  out = g_att @ Wp + bp
// Grid: (512, 6)
// ---------------------------------------------------------------------------
__global__ __launch_bounds__(256) void proj_kernel(
    const float* __restrict__ Wp,
    const float* __restrict__ bp,
    float* __restrict__ out)
{
    __shared__ float As[16][68];
    __shared__ float Bs[16][64];

    const int m0 = blockIdx.x * 64;
    const int n0 = blockIdx.y * 64;

    const int tid = threadIdx.x;
    const int ty = tid / 16, tx = tid % 16;
    const int arow = tid / 4, akv = (tid % 4) * 4;
    const int bk = tid / 16, bd = (tid % 16) * 4;

    float acc[4][4] = {};

    for (int k0 = 0; k0 < CC; k0 += 16) {
        __syncthreads();
        float4 av = *(const float4*)&g_att[(size_t)(m0 + arow) * CC + k0 + akv];
        As[akv + 0][arow] = av.x;
        As[akv + 1][arow] = av.y;
        As[akv + 2][arow] = av.z;
        As[akv + 3][arow] = av.w;
        *(float4*)&Bs[bk][bd] = *(const float4*)&Wp[(size_t)(k0 + bk) * CC + n0 + bd];
        __syncthreads();

        #pragma unroll
        for (int kk = 0; kk < 16; kk++) {
            float4 a = *(const float4*)&As[kk][ty * 4];
            float4 b = *(const float4*)&Bs[kk][tx * 4];
            float ar[4] = {a.x, a.y, a.z, a.w};
            float br[4] = {b.x, b.y, b.z, b.w};
            #pragma unroll
            for (int i = 0; i < 4; i++)
                #pragma unroll
                for (int j = 0; j < 4; j++)
                    acc[i][j] += ar[i] * br[j];
        }
    }

    float4 bias = *(const float4*)&bp[n0 + tx * 4];
    #pragma unroll
    for (int i = 0; i < 4; i++) {
        int m = m0 + ty * 4 + i;
        float4 r = {acc[i][0] + bias.x, acc[i][1] + bias.y,
                    acc[i][2] + bias.z, acc[i][3] + bias.w};
        *(float4*)&out[(size_t)m * CC + n0 + tx * 4] = r;
    }
}

// ---------------------------------------------------------------------------
extern "C" void kernel_launch(void* const* d_in, const int* in_sizes, int n_in,
                              void* d_out, int out_size)
{
    const float* x  = (const float*)d_in[0];
    const float* Wq = (const float*)d_in[1];
    const float* Wk = (const float*)d_in[2];
    const float* Wv = (const float*)d_in[3];
    const float* Wp = (const float*)d_in[4];
    const float* bp = (const float*)d_in[5];
    float* out = (float*)d_out;

    dim3 g1(MTOT / 64, QKVN / 64);     // (512, 18)
    qkv_kernel<<<g1, 256>>>(x, Wq, Wk, Wv);

    attn_kernel<<<BB * HH, 256>>>();   // 768 blocks

    dim3 g3(MTOT / 64, CC / 64);       // (512, 6)
    proj_kernel<<<g3, 256>>>(Wp, bp, out);
}

// round 5
// speedup vs baseline: 1.7556x; 1.7556x over previous
#include <cuda_runtime.h>
#include <cuda_bf16.h>
#include <cstdint>

#define BB   128
#define TT   256
#define CC   384
#define HH   6
#define HS   64
#define MTOT (BB*TT)

// Scratch (allocation-free rule)
__device__ float g_q[BB*HH*TT*HS];
__device__ float g_k[BB*HH*TT*HS];
__device__ float g_v[BB*HH*TT*HS];
__device__ float g_att[MTOT*CC];

// ---------------------------------------------------------------------------
// helpers
// ---------------------------------------------------------------------------
__device__ __forceinline__ uint32_t smem_u32(const void* p) {
    uint32_t a;
    asm("{ .reg .u64 t; cvta.to.shared.u64 t, %1; cvt.u32.u64 %0, t; }" : "=r"(a) : "l"(p));
    return a;
}

// D += A * B^T  (m16n8k16, bf16 in, f32 acc)
__device__ __forceinline__ void mma16816(float* c, const uint32_t* a, const uint32_t* b) {
    asm volatile(
        "mma.sync.aligned.m16n8k16.row.col.f32.bf16.bf16.f32 "
        "{%0,%1,%2,%3}, {%4,%5,%6,%7}, {%8,%9}, {%0,%1,%2,%3};"
        : "+f"(c[0]), "+f"(c[1]), "+f"(c[2]), "+f"(c[3])
        : "r"(a[0]), "r"(a[1]), "r"(a[2]), "r"(a[3]), "r"(b[0]), "r"(b[1]));
}
__device__ __forceinline__ void ldmx4(uint32_t* r, uint32_t addr) {
    asm volatile("ldmatrix.sync.aligned.m8n8.x4.shared.b16 {%0,%1,%2,%3}, [%4];"
        : "=r"(r[0]), "=r"(r[1]), "=r"(r[2]), "=r"(r[3]) : "r"(addr));
}
__device__ __forceinline__ void ldmx2(uint32_t* r, uint32_t addr) {
    asm volatile("ldmatrix.sync.aligned.m8n8.x2.shared.b16 {%0,%1}, [%2];"
        : "=r"(r[0]), "=r"(r[1]) : "r"(addr));
}

// split a pair of floats into packed bf16 hi and bf16 lo (a -> low half)
__device__ __forceinline__ void split2(float a, float b, uint32_t& hi, uint32_t& lo) {
    __nv_bfloat16 ha = __float2bfloat16(a), hb = __float2bfloat16(b);
    __nv_bfloat16 la = __float2bfloat16(a - __bfloat162float(ha));
    __nv_bfloat16 lb = __float2bfloat16(b - __bfloat162float(hb));
    hi = ((uint32_t)__bfloat16_as_ushort(hb) << 16) | __bfloat16_as_ushort(ha);
    lo = ((uint32_t)__bfloat16_as_ushort(lb) << 16) | __bfloat16_as_ushort(la);
}
__device__ __forceinline__ void split1(float a, __nv_bfloat16& h, __nv_bfloat16& l) {
    h = __float2bfloat16(a);
    l = __float2bfloat16(a - __bfloat162float(h));
}

// ---------------------------------------------------------------------------
// GEMM: C[128,192] tiles. MODE 0: qkv (per-head Q|K|V). MODE 1: out proj.
// smem (dynamic): AH 0..10240, AL 10240, BH 20480..+15360, BL 35840. tot 51200
// row stride 40 halves (80B, 16B-aligned, ldmatrix conflict-free)
// ---------------------------------------------------------------------------
#define GEMM_SMEM 51200
#define GA_H 0
#define GA_L 10240
#define GB_H 20480
#define GB_L 35840

template <int MODE>
__global__ __launch_bounds__(256, 1) void gemm_kernel(
    const float* __restrict__ Ain,
    const float* __restrict__ W0,
    const float* __restrict__ W1,
    const float* __restrict__ W2,
    const float* __restrict__ bp,
    float* __restrict__ out)
{
    extern __shared__ char sm[];
    const uint32_t sb = smem_u32(sm);
    uint32_t* AH32 = (uint32_t*)(sm + GA_H);
    uint32_t* AL32 = (uint32_t*)(sm + GA_L);
    __nv_bfloat16* BH = (__nv_bfloat16*)(sm + GB_H);
    __nv_bfloat16* BL = (__nv_bfloat16*)(sm + GB_L);

    const int tid  = threadIdx.x;
    const int lane = tid & 31;
    const int warp = tid >> 5;
    const int wm = warp & 3;      // row group (32 rows)
    const int wn = warp >> 2;     // col group (96 cols)

    const int m0   = blockIdx.x * 128;
    const int head = (MODE == 0) ? blockIdx.y : 0;
    const int n0g  = (MODE == 1) ? blockIdx.y * 192 : 0;
    const float* A = (MODE == 0) ? Ain : g_att;

    float acc[2][12][4];
    #pragma unroll
    for (int i = 0; i < 2; i++)
        #pragma unroll
        for (int j = 0; j < 12; j++)
            #pragma unroll
            for (int e = 0; e < 4; e++) acc[i][j][e] = 0.f;

    float4 pa[4], pb[6];

    // prefetch chunk 0
    #pragma unroll
    for (int j = 0; j < 4; j++) {
        const int idx = j * 256 + tid;
        const int row = idx >> 3, k4 = (idx & 7) * 4;
        pa[j] = *(const float4*)(A + (size_t)(m0 + row) * CC + k4);
    }
    #pragma unroll
    for (int j = 0; j < 6; j++) {
        const int idx = j * 256 + tid;
        const int d4 = (idx & 15) * 4;
        const int rem = idx >> 4;
        const int sub = rem % 3, kk = rem / 3;
        const float* src;
        if (MODE == 0) {
            const float* W = (sub == 0 ? W0 : sub == 1 ? W1 : W2);
            src = W + ((size_t)head * CC + kk) * HS + d4;
        } else {
            src = W0 + (size_t)kk * CC + n0g + sub * 64 + d4;
        }
        pb[j] = *(const float4*)src;
    }

    for (int ch = 0; ch < 12; ch++) {
        if (ch) __syncthreads();

        // store A chunk (split)
        #pragma unroll
        for (int j = 0; j < 4; j++) {
            const int idx = j * 256 + tid;
            const int row = idx >> 3, k4 = (idx & 7) * 4;
            uint32_t h0, l0, h1, l1;
            split2(pa[j].x, pa[j].y, h0, l0);
            split2(pa[j].z, pa[j].w, h1, l1);
            const int o = row * 20 + (k4 >> 1);
            AH32[o] = h0; AH32[o + 1] = h1;
            AL32[o] = l0; AL32[o + 1] = l1;
        }
        // store B chunk (split + transpose to [n][k])
        #pragma unroll
        for (int j = 0; j < 6; j++) {
            const int idx = j * 256 + tid;
            const int d4 = (idx & 15) * 4;
            const int rem = idx >> 4;
            const int sub = rem % 3, kk = rem / 3;
            float vv[4] = {pb[j].x, pb[j].y, pb[j].z, pb[j].w};
            #pragma unroll
            for (int e = 0; e < 4; e++) {
                __nv_bfloat16 h, l;
                split1(vv[e], h, l);
                const int n = sub * 64 + d4 + e;
                BH[n * 40 + kk] = h;
                BL[n * 40 + kk] = l;
            }
        }
        __syncthreads();

        // prefetch next chunk
        if (ch < 11) {
            const int kc = (ch + 1) * 32;
            #pragma unroll
            for (int j = 0; j < 4; j++) {
                const int idx = j * 256 + tid;
                const int row = idx >> 3, k4 = (idx & 7) * 4;
                pa[j] = *(const float4*)(A + (size_t)(m0 + row) * CC + kc + k4);
            }
            #pragma unroll
            for (int j = 0; j < 6; j++) {
                const int idx = j * 256 + tid;
                const int d4 = (idx & 15) * 4;
                const int rem = idx >> 4;
                const int sub = rem % 3, kk = rem / 3;
                const float* src;
                if (MODE == 0) {
                    const float* W = (sub == 0 ? W0 : sub == 1 ? W1 : W2);
                    src = W + ((size_t)head * CC + kc + kk) * HS + d4;
                } else {
                    src = W0 + (size_t)(kc + kk) * CC + n0g + sub * 64 + d4;
                }
                pb[j] = *(const float4*)src;
            }
        }

        // compute: 2 k16 steps
        #pragma unroll
        for (int k16 = 0; k16 < 2; k16++) {
            uint32_t ah[2][4], al[2][4];
            #pragma unroll
            for (int mt = 0; mt < 2; mt++) {
                const int row = wm * 32 + mt * 16 + (lane & 15);
                const int col = k16 * 16 + (lane >> 4) * 8;
                const uint32_t off = (uint32_t)(row * 40 + col) * 2;
                ldmx4(ah[mt], sb + GA_H + off);
                ldmx4(al[mt], sb + GA_L + off);
            }
            #pragma unroll
            for (int nt = 0; nt < 12; nt++) {
                const int nrow = wn * 96 + nt * 8 + (lane & 7);
                const int col = k16 * 16 + ((lane >> 3) & 1) * 8;
                const uint32_t off = (uint32_t)(nrow * 40 + col) * 2;
                uint32_t bh2[2], bl2[2];
                ldmx2(bh2, sb + GB_H + off);
                ldmx2(bl2, sb + GB_L + off);
                #pragma unroll
                for (int mt = 0; mt < 2; mt++) {
                    mma16816(acc[mt][nt], ah[mt], bh2);
                    mma16816(acc[mt][nt], al[mt], bh2);
                    mma16816(acc[mt][nt], ah[mt], bl2);
                }
            }
        }
    }

    // epilogue
    const int g = lane >> 2, tg = lane & 3;
    #pragma unroll
    for (int mt = 0; mt < 2; mt++) {
        #pragma unroll
        for (int rh = 0; rh < 2; rh++) {
            const int m = m0 + wm * 32 + mt * 16 + g + rh * 8;
            #pragma unroll
            for (int nt = 0; nt < 12; nt++) {
                const int col = wn * 96 + nt * 8 + tg * 2;
                float2 v = {acc[mt][nt][rh * 2], acc[mt][nt][rh * 2 + 1]};
                if (MODE == 0) {
                    const int sub = col >> 6, d = col & 63;
                    float* base = (sub == 0 ? g_q : sub == 1 ? g_k : g_v);
                    const int b = m >> 8, t = m & 255;
                    *(float2*)(base + (((size_t)(b * HH + head) * TT + t) * HS) + d) = v;
                } else {
                    const int n = n0g + col;
                    v.x += bp[n]; v.y += bp[n + 1];
                    *(float2*)(out + (size_t)m * CC + n) = v;
                }
            }
        }
    }
}

// ---------------------------------------------------------------------------
// Attention: flash-2 with mma.sync split-bf16.
// Block = (b,h,half): 128 q rows, 8 warps x 16 rows. K/V chunks of 64 keys.
// smem (dynamic, 144B row stride = 72 halves):
//   QH 0 (18432), QL 18432, KH 36864 (9216), KL 46080, VTH 55296, VTL 64512
//   total 73728
// ---------------------------------------------------------------------------
#define ATT_SMEM 73728
#define AQ_H 0
#define AQ_L 18432
#define AK_H 36864
#define AK_L 46080
#define AV_H 55296
#define AV_L 64512

__global__ __launch_bounds__(256, 1) void attn_kernel()
{
    extern __shared__ char sm[];
    const uint32_t sb = smem_u32(sm);
    uint32_t* QH32 = (uint32_t*)(sm + AQ_H);
    uint32_t* QL32 = (uint32_t*)(sm + AQ_L);
    uint32_t* KH32 = (uint32_t*)(sm + AK_H);
    uint32_t* KL32 = (uint32_t*)(sm + AK_L);
    __nv_bfloat16* VTH = (__nv_bfloat16*)(sm + AV_H);
    __nv_bfloat16* VTL = (__nv_bfloat16*)(sm + AV_L);

    const int bid = blockIdx.x;
    const int bh = bid >> 1, half = bid & 1;
    const int b = bh / HH, h = bh % HH;
    const int qbase = half * 128;

    const float* qg = g_q + (size_t)bh * TT * HS;
    const float* kg = g_k + (size_t)bh * TT * HS;
    const float* vg = g_v + (size_t)bh * TT * HS;

    const int tid  = threadIdx.x;
    const int lane = tid & 31;
    const int warp = tid >> 5;
    const int g = lane >> 2, tg = lane & 3;

    // ---- stage Q (scaled by 1/8) into smem hi/lo
    #pragma unroll
    for (int j = 0; j < 8; j++) {
        const int idx = j * 256 + tid;
        const int row = idx >> 4, d4 = (idx & 15) * 4;
        float4 v = *(const float4*)(qg + (size_t)(qbase + row) * HS + d4);
        uint32_t h0, l0, h1, l1;
        split2(v.x * 0.125f, v.y * 0.125f, h0, l0);
        split2(v.z * 0.125f, v.w * 0.125f, h1, l1);
        const int o = row * 36 + (d4 >> 1);
        QH32[o] = h0; QH32[o + 1] = h1;
        QL32[o] = l0; QL32[o + 1] = l1;
    }
    __syncthreads();

    // ---- Q fragments (persistent)
    uint32_t qh[4][4], ql[4][4];
    #pragma unroll
    for (int kt = 0; kt < 4; kt++) {
        const int row = warp * 16 + (lane & 15);
        const int col = kt * 16 + (lane >> 4) * 8;
        const uint32_t off = (uint32_t)(row * 72 + col) * 2;
        ldmx4(qh[kt], sb + AQ_H + off);
        ldmx4(ql[kt], sb + AQ_L + off);
    }

    float o[8][4];
    #pragma unroll
    for (int i = 0; i < 8; i++)
        #pragma unroll
        for (int e = 0; e < 4; e++) o[i][e] = 0.f;
    float m0r = -1e30f, m1r = -1e30f, l0s = 0.f, l1s = 0.f;

    const int nch = (half == 0) ? 2 : 4;
    const int wmax = qbase + warp * 16 + 15;

    for (int c = 0; c < nch; c++) {
        const int j0 = c * 64;
        __syncthreads();
        // ---- stage K chunk (natural [key][d]) and V chunk (transposed [d][key])
        #pragma unroll
        for (int j = 0; j < 4; j++) {
            const int idx = j * 256 + tid;
            const int row = idx >> 4, d4 = (idx & 15) * 4;
            float4 kv = *(const float4*)(kg + (size_t)(j0 + row) * HS + d4);
            uint32_t h0, l0, h1, l1;
            split2(kv.x, kv.y, h0, l0);
            split2(kv.z, kv.w, h1, l1);
            const int ko = row * 36 + (d4 >> 1);
            KH32[ko] = h0; KH32[ko + 1] = h1;
            KL32[ko] = l0; KL32[ko + 1] = l1;

            float4 vv = *(const float4*)(vg + (size_t)(j0 + row) * HS + d4);
            float ve[4] = {vv.x, vv.y, vv.z, vv.w};
            #pragma unroll
            for (int e = 0; e < 4; e++) {
                __nv_bfloat16 hh, ll;
                split1(ve[e], hh, ll);
                VTH[(d4 + e) * 72 + row] = hh;
                VTL[(d4 + e) * 72 + row] = ll;
            }
        }
        __syncthreads();

        if (j0 > wmax) continue;

        // ---- S = Q K^T
        float s[8][4];
        #pragma unroll
        for (int i = 0; i < 8; i++)
            #pragma unroll
            for (int e = 0; e < 4; e++) s[i][e] = 0.f;

        #pragma unroll
        for (int nt = 0; nt < 8; nt++) {
            const int nrow = nt * 8 + (lane & 7);
            #pragma unroll
            for (int kt = 0; kt < 4; kt++) {
                const int col = kt * 16 + ((lane >> 3) & 1) * 8;
                const uint32_t off = (uint32_t)(nrow * 72 + col) * 2;
                uint32_t bh2[2], bl2[2];
                ldmx2(bh2, sb + AK_H + off);
                ldmx2(bl2, sb + AK_L + off);
                mma16816(s[nt], qh[kt], bh2);
                mma16816(s[nt], ql[kt], bh2);
                mma16816(s[nt], qh[kt], bl2);
            }
        }

        // ---- causal mask
        const int row0 = qbase + warp * 16 + g;
        const int row1 = row0 + 8;
        #pragma unroll
        for (int nt = 0; nt < 8; nt++) {
            #pragma unroll
            for (int e = 0; e < 2; e++) {
                const int key = j0 + nt * 8 + tg * 2 + e;
                if (key > row0) s[nt][e] = -1e30f;
                if (key > row1) s[nt][2 + e] = -1e30f;
            }
        }

        // ---- online softmax
        float vm0 = -1e30f, vm1 = -1e30f;
        #pragma unroll
        for (int nt = 0; nt < 8; nt++) {
            vm0 = fmaxf(vm0, fmaxf(s[nt][0], s[nt][1]));
            vm1 = fmaxf(vm1, fmaxf(s[nt][2], s[nt][3]));
        }
        vm0 = fmaxf(vm0, __shfl_xor_sync(0xffffffffu, vm0, 1));
        vm0 = fmaxf(vm0, __shfl_xor_sync(0xffffffffu, vm0, 2));
        vm1 = fmaxf(vm1, __shfl_xor_sync(0xffffffffu, vm1, 1));
        vm1 = fmaxf(vm1, __shfl_xor_sync(0xffffffffu, vm1, 2));

        const float nm0 = fmaxf(m0r, vm0), nm1 = fmaxf(m1r, vm1);
        const float corr0 = __expf(m0r - nm0), corr1 = __expf(m1r - nm1);
        m0r = nm0; m1r = nm1;

        float ps0 = 0.f, ps1 = 0.f;
        #pragma unroll
        for (int nt = 0; nt < 8; nt++) {
            s[nt][0] = __expf(s[nt][0] - nm0);
            s[nt][1] = __expf(s[nt][1] - nm0);
            s[nt][2] = __expf(s[nt][2] - nm1);
            s[nt][3] = __expf(s[nt][3] - nm1);
            ps0 += s[nt][0] + s[nt][1];
            ps1 += s[nt][2] + s[nt][3];
        }
        ps0 += __shfl_xor_sync(0xffffffffu, ps0, 1);
        ps0 += __shfl_xor_sync(0xffffffffu, ps0, 2);
        ps1 += __shfl_xor_sync(0xffffffffu, ps1, 1);
        ps1 += __shfl_xor_sync(0xffffffffu, ps1, 2);
        l0s = l0s * corr0 + ps0;
        l1s = l1s * corr1 + ps1;
        #pragma unroll
        for (int nt = 0; nt < 8; nt++) {
            o[nt][0] *= corr0; o[nt][1] *= corr0;
            o[nt][2] *= corr1; o[nt][3] *= corr1;
        }

        // ---- P fragments (split), from S regs directly (C-frag == A-frag layout)
        uint32_t ph[4][4], pl[4][4];
        #pragma unroll
        for (int kt = 0; kt < 4; kt++) {
            split2(s[2 * kt][0],     s[2 * kt][1],     ph[kt][0], pl[kt][0]);
            split2(s[2 * kt][2],     s[2 * kt][3],     ph[kt][1], pl[kt][1]);
            split2(s[2 * kt + 1][0], s[2 * kt + 1][1], ph[kt][2], pl[kt][2]);
            split2(s[2 * kt + 1][2], s[2 * kt + 1][3], ph[kt][3], pl[kt][3]);
        }

        // ---- O += P V
        #pragma unroll
        for (int nt = 0; nt < 8; nt++) {
            const int nrow = nt * 8 + (lane & 7);
            #pragma unroll
            for (int kt = 0; kt < 4; kt++) {
                const int col = kt * 16 + ((lane >> 3) & 1) * 8;
                const uint32_t off = (uint32_t)(nrow * 72 + col) * 2;
                uint32_t vh2[2], vl2[2];
                ldmx2(vh2, sb + AV_H + off);
                ldmx2(vl2, sb + AV_L + off);
                mma16816(o[nt], ph[kt], vh2);
                mma16816(o[nt], pl[kt], vh2);
                mma16816(o[nt], ph[kt], vl2);
            }
        }
    }

    // ---- write O / l
    const float inv0 = 1.f / l0s, inv1 = 1.f / l1s;
    const int row0 = qbase + warp * 16 + g;
    const int row1 = row0 + 8;
    #pragma unroll
    for (int nt = 0; nt < 8; nt++) {
        const int col = h * 64 + nt * 8 + tg * 2;
        float2 v0 = {o[nt][0] * inv0, o[nt][1] * inv0};
        float2 v1 = {o[nt][2] * inv1, o[nt][3] * inv1};
        *(float2*)(g_att + (size_t)(b * TT + row0) * CC + col) = v0;
        *(float2*)(g_att + (size_t)(b * TT + row1) * CC + col) = v1;
    }
}

// ---------------------------------------------------------------------------
extern "C" void kernel_launch(void* const* d_in, const int* in_sizes, int n_in,
                              void* d_out, int out_size)
{
    const float* x  = (const float*)d_in[0];
    const float* Wq = (const float*)d_in[1];
    const float* Wk = (const float*)d_in[2];
    const float* Wv = (const float*)d_in[3];
    const float* Wp = (const float*)d_in[4];
    const float* bp = (const float*)d_in[5];
    float* out = (float*)d_out;

    cudaFuncSetAttribute(gemm_kernel<0>, cudaFuncAttributeMaxDynamicSharedMemorySize, GEMM_SMEM);
    cudaFuncSetAttribute(gemm_kernel<1>, cudaFuncAttributeMaxDynamicSharedMemorySize, GEMM_SMEM);
    cudaFuncSetAttribute(attn_kernel,    cudaFuncAttributeMaxDynamicSharedMemorySize, ATT_SMEM);

    dim3 g1(MTOT / 128, HH);        // (256, 6)
    gemm_kernel<0><<<g1, 256, GEMM_SMEM>>>(x, Wq, Wk, Wv, nullptr, nullptr);

    attn_kernel<<<BB * HH * 2, 256, ATT_SMEM>>>();   // 1536 blocks

    dim3 g3(MTOT / 128, CC / 192);  // (256, 2)
    gemm_kernel<1><<<g3, 256, GEMM_SMEM>>>(nullptr, Wp, nullptr, nullptr, bp, out);
}

// round 10
// speedup vs baseline: 3.6121x; 2.0575x over previous
#include <cuda_runtime.h>
#include <cuda_bf16.h>
#include <cstdint>

#define BB   128
#define TT   256
#define CC   384
#define HH   6
#define HS   64
#define MTOT (BB*TT)
#define QKV_E 12582912     // = MTOT*CC = BB*HH*TT*HS

// ---------------------------------------------------------------------------
// Pre-split bf16 hi/lo scratch (allocation-free rule: __device__ globals)
// ---------------------------------------------------------------------------
__device__ __nv_bfloat16 g_xh[QKV_E], g_xl[QKV_E];        // x          [m][384]
__device__ __nv_bfloat16 g_qh[QKV_E], g_ql[QKV_E];        // q (scaled) [bh][t][64]
__device__ __nv_bfloat16 g_kh[QKV_E], g_kl[QKV_E];
__device__ __nv_bfloat16 g_vh[QKV_E], g_vl[QKV_E];
__device__ __nv_bfloat16 g_ah[QKV_E], g_al[QKV_E];        // attn out   [m][384]
__device__ __nv_bfloat16 g_wh[1536*384], g_wl[1536*384];  // Wall(1152)+Wpt(384), [n][k]

// ---------------------------------------------------------------------------
// helpers
// ---------------------------------------------------------------------------
__device__ __forceinline__ uint32_t smem_u32(const void* p) {
    uint32_t a;
    asm("{ .reg .u64 t; cvta.to.shared.u64 t, %1; cvt.u32.u64 %0, t; }" : "=r"(a) : "l"(p));
    return a;
}
__device__ __forceinline__ void mma16816(float* c, const uint32_t* a, const uint32_t* b) {
    asm volatile(
        "mma.sync.aligned.m16n8k16.row.col.f32.bf16.bf16.f32 "
        "{%0,%1,%2,%3}, {%4,%5,%6,%7}, {%8,%9}, {%0,%1,%2,%3};"
        : "+f"(c[0]), "+f"(c[1]), "+f"(c[2]), "+f"(c[3])
        : "r"(a[0]), "r"(a[1]), "r"(a[2]), "r"(a[3]), "r"(b[0]), "r"(b[1]));
}
__device__ __forceinline__ void ldmx4(uint32_t* r, uint32_t addr) {
    asm volatile("ldmatrix.sync.aligned.m8n8.x4.shared.b16 {%0,%1,%2,%3}, [%4];"
        : "=r"(r[0]), "=r"(r[1]), "=r"(r[2]), "=r"(r[3]) : "r"(addr));
}
__device__ __forceinline__ void ldmx2(uint32_t* r, uint32_t addr) {
    asm volatile("ldmatrix.sync.aligned.m8n8.x2.shared.b16 {%0,%1}, [%2];"
        : "=r"(r[0]), "=r"(r[1]) : "r"(addr));
}
#define CP16(dst, src) asm volatile("cp.async.ca.shared.global [%0], [%1], 16;" :: "r"(dst), "l"(src))
#define CP_COMMIT()    asm volatile("cp.async.commit_group;")
#define CP_WAIT(n)     asm volatile("cp.async.wait_group %0;" :: "n"(n))

__device__ __forceinline__ void split2(float a, float b, uint32_t& hi, uint32_t& lo) {
    __nv_bfloat16 ha = __float2bfloat16(a), hb = __float2bfloat16(b);
    __nv_bfloat16 la = __float2bfloat16(a - __bfloat162float(ha));
    __nv_bfloat16 lb = __float2bfloat16(b - __bfloat162float(hb));
    hi = ((uint32_t)__bfloat16_as_ushort(hb) << 16) | __bfloat16_as_ushort(ha);
    lo = ((uint32_t)__bfloat16_as_ushort(lb) << 16) | __bfloat16_as_ushort(la);
}
__device__ __forceinline__ void split1(float a, __nv_bfloat16& h, __nv_bfloat16& l) {
    h = __float2bfloat16(a);
    l = __float2bfloat16(a - __bfloat162float(h));
}

// ---------------------------------------------------------------------------
// convert kernels (one-shot, bandwidth-bound)
// ---------------------------------------------------------------------------
__global__ __launch_bounds__(256) void conv_x(const float* __restrict__ x) {
    const int i = blockIdx.x * 256 + threadIdx.x;     // per float4
    float4 v = ((const float4*)x)[i];
    uint32_t h0, l0, h1, l1;
    split2(v.x, v.y, h0, l0);
    split2(v.z, v.w, h1, l1);
    ((uint32_t*)g_xh)[2 * i] = h0;  ((uint32_t*)g_xh)[2 * i + 1] = h1;
    ((uint32_t*)g_xl)[2 * i] = l0;  ((uint32_t*)g_xl)[2 * i + 1] = l1;
}

__global__ __launch_bounds__(256) void conv_w(
    const float* __restrict__ Wq, const float* __restrict__ Wk,
    const float* __restrict__ Wv, const float* __restrict__ Wp)
{
    const int i = blockIdx.x * 256 + threadIdx.x;     // 1536*384 elements
    const int row = i / 384, k = i % 384;
    float val;
    if (row < 1152) {
        const int t = row / 384, rem = row % 384, h = rem / 64, d = rem % 64;
        const float* W = (t == 0 ? Wq : t == 1 ? Wk : Wv);
        val = W[((size_t)h * 384 + k) * 64 + d];
    } else {
        const int n = row - 1152;
        val = Wp[(size_t)k * 384 + n];
    }
    __nv_bfloat16 hh, ll;
    split1(val, hh, ll);
    g_wh[i] = hh;
    g_wl[i] = ll;
}

// ---------------------------------------------------------------------------
// GEMM: C[128,128] tiles over pre-split bf16. A [m][384], B [n][384].
// 8 warps: wm 0..3 (32 rows), wn 0..1 (64 cols). cp.async double buffer.
// stage: A_H 0, A_L 10240, B_H 20480, B_L 30720 (stride 40 halves); 40960/stage
// ---------------------------------------------------------------------------
#define GEMM_SMEM 81920

template <int MODE>
__global__ __launch_bounds__(256, 2) void gemm_kernel(
    const __nv_bfloat16* __restrict__ Ah, const __nv_bfloat16* __restrict__ Al,
    const __nv_bfloat16* __restrict__ Bh, const __nv_bfloat16* __restrict__ Bl,
    const float* __restrict__ bp, float* __restrict__ out)
{
    extern __shared__ char sm[];
    const uint32_t sb = smem_u32(sm);

    const int tid  = threadIdx.x;
    const int lane = tid & 31;
    const int warp = tid >> 5;
    const int wm = warp & 3;
    const int wn = warp >> 2;

    const int m0 = blockIdx.x * 128;
    const int n0 = blockIdx.y * 128;

    // cp.async per-thread coords: 512 txn per component, 2 rows per thread
    const int rowL = tid >> 2;             // 0..63 (second row = +64)
    const int segL = (tid & 3) * 8;        // halves
    const uint32_t soBase = (uint32_t)(rowL * 40 + segL) * 2;

    float acc[2][8][4];
    #pragma unroll
    for (int i = 0; i < 2; i++)
        #pragma unroll
        for (int j = 0; j < 8; j++)
            #pragma unroll
            for (int e = 0; e < 4; e++) acc[i][j][e] = 0.f;

    auto issue = [&](int ch, int s) {
        const uint32_t base = sb + s * 40960;
        const int kof = ch * 32 + segL;
        #pragma unroll
        for (int r = 0; r < 2; r++) {
            const int row = rowL + r * 64;
            const uint32_t so = soBase + r * 64 * 80;
            CP16(base +         so, Ah + (size_t)(m0 + row) * 384 + kof);
            CP16(base + 10240 + so, Al + (size_t)(m0 + row) * 384 + kof);
            CP16(base + 20480 + so, Bh + (size_t)(n0 + row) * 384 + kof);
            CP16(base + 30720 + so, Bl + (size_t)(n0 + row) * 384 + kof);
        }
    };

    issue(0, 0);
    CP_COMMIT();

    for (int ch = 0; ch < 12; ch++) {
        if (ch + 1 < 12) { issue(ch + 1, (ch + 1) & 1); CP_COMMIT(); CP_WAIT(1); }
        else             { CP_WAIT(0); }
        __syncthreads();

        const uint32_t sbuf = sb + (ch & 1) * 40960;
        #pragma unroll
        for (int k16 = 0; k16 < 2; k16++) {
            uint32_t ah[2][4], al[2][4];
            #pragma unroll
            for (int mt = 0; mt < 2; mt++) {
                const int row = wm * 32 + mt * 16 + (lane & 15);
                const int col = k16 * 16 + (lane >> 4) * 8;
                const uint32_t off = (uint32_t)(row * 40 + col) * 2;
                ldmx4(ah[mt], sbuf + off);
                ldmx4(al[mt], sbuf + 10240 + off);
            }
            #pragma unroll
            for (int nt = 0; nt < 8; nt++) {
                const int nrow = wn * 64 + nt * 8 + (lane & 7);
                const int col = k16 * 16 + ((lane >> 3) & 1) * 8;
                const uint32_t off = (uint32_t)(nrow * 40 + col) * 2;
                uint32_t bh2[2], bl2[2];
                ldmx2(bh2, sbuf + 20480 + off);
                ldmx2(bl2, sbuf + 30720 + off);
                #pragma unroll
                for (int mt = 0; mt < 2; mt++) {
                    mma16816(acc[mt][nt], ah[mt], bh2);
                    mma16816(acc[mt][nt], al[mt], bh2);
                    mma16816(acc[mt][nt], ah[mt], bl2);
                }
            }
        }
        __syncthreads();
    }

    // ---- epilogue
    const int g = lane >> 2, tg = lane & 3;
    if (MODE == 0) {
        const int t_sel = blockIdx.y / 3;
        const int h = ((n0 % 384) / 64) + wn;
        __nv_bfloat16 *dh, *dl;
        float scale = 1.f;
        if (t_sel == 0)      { dh = g_qh; dl = g_ql; scale = 0.125f; }
        else if (t_sel == 1) { dh = g_kh; dl = g_kl; }
        else                 { dh = g_vh; dl = g_vl; }
        #pragma unroll
        for (int mt = 0; mt < 2; mt++) {
            #pragma unroll
            for (int rh = 0; rh < 2; rh++) {
                const int m = m0 + wm * 32 + mt * 16 + g + rh * 8;
                const int b = m >> 8, t = m & 255;
                const size_t base = ((size_t)(b * HH + h) * TT + t) * HS;
                #pragma unroll
                for (int nt = 0; nt < 8; nt++) {
                    const int d = nt * 8 + tg * 2;
                    uint32_t hi, lo;
                    split2(acc[mt][nt][rh * 2] * scale, acc[mt][nt][rh * 2 + 1] * scale, hi, lo);
                    *(uint32_t*)(dh + base + d) = hi;
                    *(uint32_t*)(dl + base + d) = lo;
                }
            }
        }
    } else {
        #pragma unroll
        for (int mt = 0; mt < 2; mt++) {
            #pragma unroll
            for (int rh = 0; rh < 2; rh++) {
                const int m = m0 + wm * 32 + mt * 16 + g + rh * 8;
                #pragma unroll
                for (int nt = 0; nt < 8; nt++) {
                    const int n = n0 + wn * 64 + nt * 8 + tg * 2;
                    float2 v = {acc[mt][nt][rh * 2] + bp[n], acc[mt][nt][rh * 2 + 1] + bp[n + 1]};
                    *(float2*)(out + (size_t)m * CC + n) = v;
                }
            }
        }
    }
}

// ---------------------------------------------------------------------------
// Attention: flash-2 mma.sync on pre-split bf16.
// Block = (b,h,half): 128 q rows, 8 warps x 16 rows. K/V chunks of 64 keys.
// smem stride 72 halves: QH 0, QL 18432, KH 36864, KL 46080, VTH 55296, VTL 64512
// ---------------------------------------------------------------------------
#define ATT_SMEM 73728
#define AQ_H 0
#define AQ_L 18432
#define AK_H 36864
#define AK_L 46080
#define AV_H 55296
#define AV_L 64512

__global__ __launch_bounds__(256) void attn_kernel()
{
    extern __shared__ char sm[];
    const uint32_t sb = smem_u32(sm);
    __nv_bfloat16* VTH = (__nv_bfloat16*)(sm + AV_H);
    __nv_bfloat16* VTL = (__nv_bfloat16*)(sm + AV_L);

    const int bid = blockIdx.x;
    const int bh = bid >> 1, half = bid & 1;
    const int b = bh / HH, h = bh % HH;
    const int qbase = half * 128;

    const int tid  = threadIdx.x;
    const int lane = tid & 31;
    const int warp = tid >> 5;
    const int g = lane >> 2, tg = lane & 3;

    // ---- stage Q hi/lo (already scaled in gemm epilogue)
    {
        const size_t qrow0 = (size_t)bh * TT + qbase;
        #pragma unroll
        for (int r = 0; r < 4; r++) {
            const int idx = r * 256 + tid;
            const int row = idx >> 3, seg = (idx & 7) * 8;
            const uint32_t so = (uint32_t)(row * 72 + seg) * 2;
            CP16(sb + AQ_H + so, g_qh + (qrow0 + row) * HS + seg);
            CP16(sb + AQ_L + so, g_ql + (qrow0 + row) * HS + seg);
        }
        CP_COMMIT(); CP_WAIT(0);
    }
    __syncthreads();

    uint32_t qh[4][4], ql[4][4];
    #pragma unroll
    for (int kt = 0; kt < 4; kt++) {
        const int row = warp * 16 + (lane & 15);
        const int col = kt * 16 + (lane >> 4) * 8;
        const uint32_t off = (uint32_t)(row * 72 + col) * 2;
        ldmx4(qh[kt], sb + AQ_H + off);
        ldmx4(ql[kt], sb + AQ_L + off);
    }

    float o[8][4];
    #pragma unroll
    for (int i = 0; i < 8; i++)
        #pragma unroll
        for (int e = 0; e < 4; e++) o[i][e] = 0.f;
    float m0r = -1e30f, m1r = -1e30f, l0s = 0.f, l1s = 0.f;

    const int nch = (half == 0) ? 2 : 4;
    const int wmax = qbase + warp * 16 + 15;

    for (int c = 0; c < nch; c++) {
        const int j0 = c * 64;
        __syncthreads();
        // K via cp.async
        {
            const size_t krow0 = (size_t)bh * TT + j0;
            #pragma unroll
            for (int r = 0; r < 2; r++) {
                const int idx = r * 256 + tid;
                const int row = idx >> 3, seg = (idx & 7) * 8;
                const uint32_t so = (uint32_t)(row * 72 + seg) * 2;
                CP16(sb + AK_H + so, g_kh + (krow0 + row) * HS + seg);
                CP16(sb + AK_L + so, g_kl + (krow0 + row) * HS + seg);
            }
            CP_COMMIT();
        }
        // V transpose: [t][d] -> [d][t] via register staging (staggered banks)
        {
            const size_t vrow0 = (size_t)bh * TT + j0;
            #pragma unroll
            for (int r = 0; r < 2; r++) {
                const int idx = r * 256 + tid;
                const int row = idx >> 3, d8 = (idx & 7) * 8;
                uint4 vh4 = *(const uint4*)(g_vh + (vrow0 + row) * HS + d8);
                uint4 vl4 = *(const uint4*)(g_vl + (vrow0 + row) * HS + d8);
                const unsigned short* ph = (const unsigned short*)&vh4;
                const unsigned short* pl = (const unsigned short*)&vl4;
                #pragma unroll
                for (int ee = 0; ee < 8; ee++) {
                    const int e = (ee + (lane & 7)) & 7;
                    ((unsigned short*)VTH)[(d8 + e) * 72 + row] = ph[e];
                    ((unsigned short*)VTL)[(d8 + e) * 72 + row] = pl[e];
                }
            }
        }
        CP_WAIT(0);
        __syncthreads();

        if (j0 > wmax) continue;

        // ---- S = Q K^T
        float s[8][4];
        #pragma unroll
        for (int i = 0; i < 8; i++)
            #pragma unroll
            for (int e = 0; e < 4; e++) s[i][e] = 0.f;

        #pragma unroll
        for (int nt = 0; nt < 8; nt++) {
            const int nrow = nt * 8 + (lane & 7);
            #pragma unroll
            for (int kt = 0; kt < 4; kt++) {
                const int col = kt * 16 + ((lane >> 3) & 1) * 8;
                const uint32_t off = (uint32_t)(nrow * 72 + col) * 2;
                uint32_t bh2[2], bl2[2];
                ldmx2(bh2, sb + AK_H + off);
                ldmx2(bl2, sb + AK_L + off);
                mma16816(s[nt], qh[kt], bh2);
                mma16816(s[nt], ql[kt], bh2);
                mma16816(s[nt], qh[kt], bl2);
            }
        }

        // ---- causal mask
        const int row0 = qbase + warp * 16 + g;
        const int row1 = row0 + 8;
        #pragma unroll
        for (int nt = 0; nt < 8; nt++) {
            #pragma unroll
            for (int e = 0; e < 2; e++) {
                const int key = j0 + nt * 8 + tg * 2 + e;
                if (key > row0) s[nt][e] = -1e30f;
                if (key > row1) s[nt][2 + e] = -1e30f;
            }
        }

        // ---- online softmax
        float vm0 = -1e30f, vm1 = -1e30f;
        #pragma unroll
        for (int nt = 0; nt < 8; nt++) {
            vm0 = fmaxf(vm0, fmaxf(s[nt][0], s[nt][1]));
            vm1 = fmaxf(vm1, fmaxf(s[nt][2], s[nt][3]));
        }
        vm0 = fmaxf(vm0, __shfl_xor_sync(0xffffffffu, vm0, 1));
        vm0 = fmaxf(vm0, __shfl_xor_sync(0xffffffffu, vm0, 2));
        vm1 = fmaxf(vm1, __shfl_xor_sync(0xffffffffu, vm1, 1));
        vm1 = fmaxf(vm1, __shfl_xor_sync(0xffffffffu, vm1, 2));

        const float nm0 = fmaxf(m0r, vm0), nm1 = fmaxf(m1r, vm1);
        const float corr0 = __expf(m0r - nm0), corr1 = __expf(m1r - nm1);
        m0r = nm0; m1r = nm1;

        float ps0 = 0.f, ps1 = 0.f;
        #pragma unroll
        for (int nt = 0; nt < 8; nt++) {
            s[nt][0] = __expf(s[nt][0] - nm0);
            s[nt][1] = __expf(s[nt][1] - nm0);
            s[nt][2] = __expf(s[nt][2] - nm1);
            s[nt][3] = __expf(s[nt][3] - nm1);
            ps0 += s[nt][0] + s[nt][1];
            ps1 += s[nt][2] + s[nt][3];
        }
        ps0 += __shfl_xor_sync(0xffffffffu, ps0, 1);
        ps0 += __shfl_xor_sync(0xffffffffu, ps0, 2);
        ps1 += __shfl_xor_sync(0xffffffffu, ps1, 1);
        ps1 += __shfl_xor_sync(0xffffffffu, ps1, 2);
        l0s = l0s * corr0 + ps0;
        l1s = l1s * corr1 + ps1;
        #pragma unroll
        for (int nt = 0; nt < 8; nt++) {
            o[nt][0] *= corr0; o[nt][1] *= corr0;
            o[nt][2] *= corr1; o[nt][3] *= corr1;
        }

        // ---- P fragments (C-frag == A-frag layout)
        uint32_t ph[4][4], pl[4][4];
        #pragma unroll
        for (int kt = 0; kt < 4; kt++) {
            split2(s[2 * kt][0],     s[2 * kt][1],     ph[kt][0], pl[kt][0]);
            split2(s[2 * kt][2],     s[2 * kt][3],     ph[kt][1], pl[kt][1]);
            split2(s[2 * kt + 1][0], s[2 * kt + 1][1], ph[kt][2], pl[kt][2]);
            split2(s[2 * kt + 1][2], s[2 * kt + 1][3], ph[kt][3], pl[kt][3]);
        }

        // ---- O += P V
        #pragma unroll
        for (int nt = 0; nt < 8; nt++) {
            const int nrow = nt * 8 + (lane & 7);
            #pragma unroll
            for (int kt = 0; kt < 4; kt++) {
                const int col = kt * 16 + ((lane >> 3) & 1) * 8;
                const uint32_t off = (uint32_t)(nrow * 72 + col) * 2;
                uint32_t vh2[2], vl2[2];
                ldmx2(vh2, sb + AV_H + off);
                ldmx2(vl2, sb + AV_L + off);
                mma16816(o[nt], ph[kt], vh2);
                mma16816(o[nt], pl[kt], vh2);
                mma16816(o[nt], ph[kt], vl2);
            }
        }
    }

    // ---- write O as bf16 hi/lo into g_ah/g_al [m][384]
    const float inv0 = 1.f / l0s, inv1 = 1.f / l1s;
    const int row0 = qbase + warp * 16 + g;
    const int row1 = row0 + 8;
    #pragma unroll
    for (int nt = 0; nt < 8; nt++) {
        const int col = h * 64 + nt * 8 + tg * 2;
        uint32_t hi0, lo0, hi1, lo1;
        split2(o[nt][0] * inv0, o[nt][1] * inv0, hi0, lo0);
        split2(o[nt][2] * inv1, o[nt][3] * inv1, hi1, lo1);
        const size_t i0 = (size_t)(b * TT + row0) * CC + col;
        const size_t i1 = (size_t)(b * TT + row1) * CC + col;
        *(uint32_t*)(g_ah + i0) = hi0;  *(uint32_t*)(g_al + i0) = lo0;
        *(uint32_t*)(g_ah + i1) = hi1;  *(uint32_t*)(g_al + i1) = lo1;
    }
}

// ---------------------------------------------------------------------------
extern "C" void kernel_launch(void* const* d_in, const int* in_sizes, int n_in,
                              void* d_out, int out_size)
{
    const float* x  = (const float*)d_in[0];
    const float* Wq = (const float*)d_in[1];
    const float* Wk = (const float*)d_in[2];
    const float* Wv = (const float*)d_in[3];
    const float* Wp = (const float*)d_in[4];
    const float* bp = (const float*)d_in[5];
    float* out = (float*)d_out;

    cudaFuncSetAttribute(gemm_kernel<0>, cudaFuncAttributeMaxDynamicSharedMemorySize, GEMM_SMEM);
    cudaFuncSetAttribute(gemm_kernel<1>, cudaFuncAttributeMaxDynamicSharedMemorySize, GEMM_SMEM);
    cudaFuncSetAttribute(attn_kernel,    cudaFuncAttributeMaxDynamicSharedMemorySize, ATT_SMEM);

    conv_x<<<MTOT * CC / 4 / 256, 256>>>(x);               // 12288 blocks
    conv_w<<<1536 * 384 / 256, 256>>>(Wq, Wk, Wv, Wp);     // 2304 blocks

    __nv_bfloat16 *xh, *xl, *wh, *wl, *ah, *al;
    cudaGetSymbolAddress((void**)&xh, g_xh);
    cudaGetSymbolAddress((void**)&xl, g_xl);
    cudaGetSymbolAddress((void**)&wh, g_wh);
    cudaGetSymbolAddress((void**)&wl, g_wl);
    cudaGetSymbolAddress((void**)&ah, g_ah);
    cudaGetSymbolAddress((void**)&al, g_al);

    dim3 g1(MTOT / 128, 9);
    gemm_kernel<0><<<g1, 256, GEMM_SMEM>>>(xh, xl, wh, wl, nullptr, nullptr);

    attn_kernel<<<BB * HH * 2, 256, ATT_SMEM>>>();

    dim3 g3(MTOT / 128, 3);
    gemm_kernel<1><<<g3, 256, GEMM_SMEM>>>(ah, al, wh + 1152 * 384, wl + 1152 * 384, bp, out);
}

// round 12
// speedup vs baseline: 3.6136x; 1.0004x over previous
#include <cuda_runtime.h>
#include <cuda_bf16.h>
#include <cstdint>

#define BB   128
#define TT   256
#define CC   384
#define HH   6
#define HS   64
#define MTOT (BB*TT)
#define QKV_E 12582912     // = MTOT*CC = BB*HH*TT*HS

// ---------------------------------------------------------------------------
// Pre-split bf16 hi/lo scratch (allocation-free rule: __device__ globals)
// ---------------------------------------------------------------------------
__device__ __nv_bfloat16 g_xh[QKV_E], g_xl[QKV_E];        // x          [m][384]
__device__ __nv_bfloat16 g_qh[QKV_E], g_ql[QKV_E];        // q (scaled) [bh][t][64]
__device__ __nv_bfloat16 g_kh[QKV_E], g_kl[QKV_E];        // k          [bh][t][64]
__device__ __nv_bfloat16 g_vh[QKV_E], g_vl[QKV_E];        // V^T        [bh][d][256]
__device__ __nv_bfloat16 g_ah[QKV_E], g_al[QKV_E];        // attn out   [m][384]
__device__ __nv_bfloat16 g_wh[1536*384], g_wl[1536*384];  // Wall(1152)+Wpt(384), [n][k]

// ---------------------------------------------------------------------------
// helpers
// ---------------------------------------------------------------------------
__device__ __forceinline__ uint32_t smem_u32(const void* p) {
    uint32_t a;
    asm("{ .reg .u64 t; cvta.to.shared.u64 t, %1; cvt.u32.u64 %0, t; }" : "=r"(a) : "l"(p));
    return a;
}
__device__ __forceinline__ void mma16816(float* c, const uint32_t* a, const uint32_t* b) {
    asm volatile(
        "mma.sync.aligned.m16n8k16.row.col.f32.bf16.bf16.f32 "
        "{%0,%1,%2,%3}, {%4,%5,%6,%7}, {%8,%9}, {%0,%1,%2,%3};"
        : "+f"(c[0]), "+f"(c[1]), "+f"(c[2]), "+f"(c[3])
        : "r"(a[0]), "r"(a[1]), "r"(a[2]), "r"(a[3]), "r"(b[0]), "r"(b[1]));
}
__device__ __forceinline__ void ldmx4(uint32_t* r, uint32_t addr) {
    asm volatile("ldmatrix.sync.aligned.m8n8.x4.shared.b16 {%0,%1,%2,%3}, [%4];"
        : "=r"(r[0]), "=r"(r[1]), "=r"(r[2]), "=r"(r[3]) : "r"(addr));
}
__device__ __forceinline__ void ldmx2(uint32_t* r, uint32_t addr) {
    asm volatile("ldmatrix.sync.aligned.m8n8.x2.shared.b16 {%0,%1}, [%2];"
        : "=r"(r[0]), "=r"(r[1]) : "r"(addr));
}
#define CP16(dst, src) asm volatile("cp.async.ca.shared.global [%0], [%1], 16;" :: "r"(dst), "l"(src))
#define CP_COMMIT()    asm volatile("cp.async.commit_group;")
#define CP_WAIT(n)     asm volatile("cp.async.wait_group %0;" :: "n"(n))

__device__ __forceinline__ void split2(float a, float b, uint32_t& hi, uint32_t& lo) {
    __nv_bfloat16 ha = __float2bfloat16(a), hb = __float2bfloat16(b);
    __nv_bfloat16 la = __float2bfloat16(a - __bfloat162float(ha));
    __nv_bfloat16 lb = __float2bfloat16(b - __bfloat162float(hb));
    hi = ((uint32_t)__bfloat16_as_ushort(hb) << 16) | __bfloat16_as_ushort(ha);
    lo = ((uint32_t)__bfloat16_as_ushort(lb) << 16) | __bfloat16_as_ushort(la);
}
__device__ __forceinline__ void split1(float a, __nv_bfloat16& h, __nv_bfloat16& l) {
    h = __float2bfloat16(a);
    l = __float2bfloat16(a - __bfloat162float(h));
}

// ---------------------------------------------------------------------------
// convert kernels (one-shot, bandwidth-bound)
// ---------------------------------------------------------------------------
__global__ __launch_bounds__(256) void conv_x(const float* __restrict__ x) {
    const int i = blockIdx.x * 256 + threadIdx.x;     // per float4
    float4 v = ((const float4*)x)[i];
    uint32_t h0, l0, h1, l1;
    split2(v.x, v.y, h0, l0);
    split2(v.z, v.w, h1, l1);
    ((uint32_t*)g_xh)[2 * i] = h0;  ((uint32_t*)g_xh)[2 * i + 1] = h1;
    ((uint32_t*)g_xl)[2 * i] = l0;  ((uint32_t*)g_xl)[2 * i + 1] = l1;
}

__global__ __launch_bounds__(256) void conv_w(
    const float* __restrict__ Wq, const float* __restrict__ Wk,
    const float* __restrict__ Wv, const float* __restrict__ Wp)
{
    const int i = blockIdx.x * 256 + threadIdx.x;     // 1536*384 elements
    const int row = i / 384, k = i % 384;
    float val;
    if (row < 1152) {
        const int t = row / 384, rem = row % 384, h = rem / 64, d = rem % 64;
        const float* W = (t == 0 ? Wq : t == 1 ? Wk : Wv);
        val = W[((size_t)h * 384 + k) * 64 + d];
    } else {
        const int n = row - 1152;
        val = Wp[(size_t)k * 384 + n];
    }
    __nv_bfloat16 hh, ll;
    split1(val, hh, ll);
    g_wh[i] = hh;
    g_wl[i] = ll;
}

// ---------------------------------------------------------------------------
// GEMM: C[128,128] tiles over pre-split bf16. A [m][384], B [n][384].
// 8 warps: wm 0..3 (32 rows), wn 0..1 (64 cols). cp.async double buffer.
// ---------------------------------------------------------------------------
#define GEMM_SMEM 81920

template <int MODE>
__global__ __launch_bounds__(256, 2) void gemm_kernel(
    const __nv_bfloat16* __restrict__ Ah, const __nv_bfloat16* __restrict__ Al,
    const __nv_bfloat16* __restrict__ Bh, const __nv_bfloat16* __restrict__ Bl,
    const float* __restrict__ bp, float* __restrict__ out)
{
    extern __shared__ char sm[];
    const uint32_t sb = smem_u32(sm);

    const int tid  = threadIdx.x;
    const int lane = tid & 31;
    const int warp = tid >> 5;
    const int wm = warp & 3;
    const int wn = warp >> 2;

    const int m0 = blockIdx.x * 128;
    const int n0 = blockIdx.y * 128;

    const int rowL = tid >> 2;
    const int segL = (tid & 3) * 8;
    const uint32_t soBase = (uint32_t)(rowL * 40 + segL) * 2;

    float acc[2][8][4];
    #pragma unroll
    for (int i = 0; i < 2; i++)
        #pragma unroll
        for (int j = 0; j < 8; j++)
            #pragma unroll
            for (int e = 0; e < 4; e++) acc[i][j][e] = 0.f;

    auto issue = [&](int ch, int s) {
        const uint32_t base = sb + s * 40960;
        const int kof = ch * 32 + segL;
        #pragma unroll
        for (int r = 0; r < 2; r++) {
            const int row = rowL + r * 64;
            const uint32_t so = soBase + r * 64 * 80;
            CP16(base +         so, Ah + (size_t)(m0 + row) * 384 + kof);
            CP16(base + 10240 + so, Al + (size_t)(m0 + row) * 384 + kof);
            CP16(base + 20480 + so, Bh + (size_t)(n0 + row) * 384 + kof);
            CP16(base + 30720 + so, Bl + (size_t)(n0 + row) * 384 + kof);
        }
    };

    issue(0, 0);
    CP_COMMIT();

    for (int ch = 0; ch < 12; ch++) {
        if (ch + 1 < 12) { issue(ch + 1, (ch + 1) & 1); CP_COMMIT(); CP_WAIT(1); }
        else             { CP_WAIT(0); }
        __syncthreads();

        const uint32_t sbuf = sb + (ch & 1) * 40960;
        #pragma unroll
        for (int k16 = 0; k16 < 2; k16++) {
            uint32_t ah[2][4], al[2][4];
            #pragma unroll
            for (int mt = 0; mt < 2; mt++) {
                const int row = wm * 32 + mt * 16 + (lane & 15);
                const int col = k16 * 16 + (lane >> 4) * 8;
                const uint32_t off = (uint32_t)(row * 40 + col) * 2;
                ldmx4(ah[mt], sbuf + off);
                ldmx4(al[mt], sbuf + 10240 + off);
            }
            #pragma unroll
            for (int nt = 0; nt < 8; nt++) {
                const int nrow = wn * 64 + nt * 8 + (lane & 7);
                const int col = k16 * 16 + ((lane >> 3) & 1) * 8;
                const uint32_t off = (uint32_t)(nrow * 40 + col) * 2;
                uint32_t bh2[2], bl2[2];
                ldmx2(bh2, sbuf + 20480 + off);
                ldmx2(bl2, sbuf + 30720 + off);
                #pragma unroll
                for (int mt = 0; mt < 2; mt++) {
                    mma16816(acc[mt][nt], ah[mt], bh2);
                    mma16816(acc[mt][nt], al[mt], bh2);
                    mma16816(acc[mt][nt], ah[mt], bl2);
                }
            }
        }
        __syncthreads();
    }

    // ---- epilogue
    const int g = lane >> 2, tg = lane & 3;
    if (MODE == 0) {
        const int t_sel = blockIdx.y / 3;
        const int h = ((n0 % 384) / 64) + wn;
        if (t_sel == 2) {
            // V: write TRANSPOSED [bh][d][256] bf16 hi/lo
            unsigned short* dh = (unsigned short*)g_vh;
            unsigned short* dl = (unsigned short*)g_vl;
            #pragma unroll
            for (int mt = 0; mt < 2; mt++) {
                #pragma unroll
                for (int rh = 0; rh < 2; rh++) {
                    const int m = m0 + wm * 32 + mt * 16 + g + rh * 8;
                    const int b = m >> 8, t = m & 255;
                    const size_t bhb = (size_t)(b * HH + h) * 64;
                    #pragma unroll
                    for (int nt = 0; nt < 8; nt++) {
                        const int d = nt * 8 + tg * 2;
                        uint32_t hi, lo;
                        split2(acc[mt][nt][rh * 2], acc[mt][nt][rh * 2 + 1], hi, lo);
                        const size_t base = (bhb + d) * 256 + t;
                        dh[base] = (unsigned short)(hi & 0xffff);
                        dh[base + 256] = (unsigned short)(hi >> 16);
                        dl[base] = (unsigned short)(lo & 0xffff);
                        dl[base + 256] = (unsigned short)(lo >> 16);
                    }
                }
            }
        } else {
            __nv_bfloat16 *dh, *dl;
            float scale = 1.f;
            if (t_sel == 0) { dh = g_qh; dl = g_ql; scale = 0.125f; }
            else            { dh = g_kh; dl = g_kl; }
            #pragma unroll
            for (int mt = 0; mt < 2; mt++) {
                #pragma unroll
                for (int rh = 0; rh < 2; rh++) {
                    const int m = m0 + wm * 32 + mt * 16 + g + rh * 8;
                    const int b = m >> 8, t = m & 255;
                    const size_t base = ((size_t)(b * HH + h) * TT + t) * HS;
                    #pragma unroll
                    for (int nt = 0; nt < 8; nt++) {
                        const int d = nt * 8 + tg * 2;
                        uint32_t hi, lo;
                        split2(acc[mt][nt][rh * 2] * scale, acc[mt][nt][rh * 2 + 1] * scale, hi, lo);
                        *(uint32_t*)(dh + base + d) = hi;
                        *(uint32_t*)(dl + base + d) = lo;
                    }
                }
            }
        }
    } else {
        #pragma unroll
        for (int mt = 0; mt < 2; mt++) {
            #pragma unroll
            for (int rh = 0; rh < 2; rh++) {
                const int m = m0 + wm * 32 + mt * 16 + g + rh * 8;
                #pragma unroll
                for (int nt = 0; nt < 8; nt++) {
                    const int n = n0 + wn * 64 + nt * 8 + tg * 2;
                    float2 v = {acc[mt][nt][rh * 2] + bp[n], acc[mt][nt][rh * 2 + 1] + bp[n + 1]};
                    *(float2*)(out + (size_t)m * CC + n) = v;
                }
            }
        }
    }
}

// ---------------------------------------------------------------------------
// Attention: flash-2 mma.sync, pre-split bf16, pre-transposed V,
// double-buffered cp.async K/V staging, ldmatrix.x4 B-operands.
// Block = (b,h,half): 128 q rows, 8 warps x 16 rows. K/V chunks of 64 keys.
// smem: Q (36864) + 2 stages x 36864 (KH,KL,VH,VL @ 9216 each) = 110592
// ---------------------------------------------------------------------------
#define ATT_SMEM 110592
#define AQ_H 0
#define AQ_L 18432
#define ASTG 36864
#define SK_H 0
#define SK_L 9216
#define SV_H 18432
#define SV_L 27648

__global__ __launch_bounds__(256) void attn_kernel()
{
    extern __shared__ char sm[];
    const uint32_t sb = smem_u32(sm);

    const int bid = blockIdx.x;
    const int bh = bid >> 1, half = bid & 1;
    const int b = bh / HH, h = bh % HH;
    const int qbase = half * 128;

    const int tid  = threadIdx.x;
    const int lane = tid & 31;
    const int warp = tid >> 5;
    const int g = lane >> 2, tg = lane & 3;

    const int nch = (half == 0) ? 2 : 4;
    const int wmax = qbase + warp * 16 + 15;

    // per-thread staging coords: row = idx>>3 , seg = (idx&7)*8 halves
    const int srow = tid >> 3;          // 0..31
    const int sseg = (tid & 7) * 8;     // halves

    auto stage = [&](int c) {
        const uint32_t base = sb + ASTG + (c & 1) * 36864;
        const int j0 = c * 64;
        const size_t krow0 = (size_t)bh * TT + j0;
        const size_t vrow0 = (size_t)bh * 64;
        #pragma unroll
        for (int r = 0; r < 2; r++) {
            const int row = srow + r * 32;
            const uint32_t so = (uint32_t)(row * 72 + sseg) * 2;
            CP16(base + SK_H + so, g_kh + (krow0 + row) * HS + sseg);
            CP16(base + SK_L + so, g_kl + (krow0 + row) * HS + sseg);
            CP16(base + SV_H + so, g_vh + (vrow0 + row) * 256 + j0 + sseg);
            CP16(base + SV_L + so, g_vl + (vrow0 + row) * 256 + j0 + sseg);
        }
    };

    // ---- stage Q hi/lo (already scaled in gemm epilogue)
    {
        const size_t qrow0 = (size_t)bh * TT + qbase;
        #pragma unroll
        for (int r = 0; r < 4; r++) {
            const int idx = r * 256 + tid;
            const int row = idx >> 3, seg = (idx & 7) * 8;
            const uint32_t so = (uint32_t)(row * 72 + seg) * 2;
            CP16(sb + AQ_H + so, g_qh + (qrow0 + row) * HS + seg);
            CP16(sb + AQ_L + so, g_ql + (qrow0 + row) * HS + seg);
        }
        CP_COMMIT();
    }
    stage(0);
    CP_COMMIT();
    CP_WAIT(1);            // Q resident; stage0 may still be in flight
    __syncthreads();

    uint32_t qh[4][4], ql[4][4];
    #pragma unroll
    for (int kt = 0; kt < 4; kt++) {
        const int row = warp * 16 + (lane & 15);
        const int col = kt * 16 + (lane >> 4) * 8;
        const uint32_t off = (uint32_t)(row * 72 + col) * 2;
        ldmx4(qh[kt], sb + AQ_H + off);
        ldmx4(ql[kt], sb + AQ_L + off);
    }

    float o[8][4];
    #pragma unroll
    for (int i = 0; i < 8; i++)
        #pragma unroll
        for (int e = 0; e < 4; e++) o[i][e] = 0.f;
    float m0r = -1e30f, m1r = -1e30f, l0s = 0.f, l1s = 0.f;

    for (int c = 0; c < nch; c++) {
        const int j0 = c * 64;
        if (c + 1 < nch) { stage(c + 1); CP_COMMIT(); CP_WAIT(1); }
        else             { CP_WAIT(0); }
        __syncthreads();

        if (j0 <= wmax) {
            const uint32_t stg = sb + ASTG + (c & 1) * 36864;

            // ---- S = Q K^T
            float s[8][4];
            #pragma unroll
            for (int i = 0; i < 8; i++)
                #pragma unroll
                for (int e = 0; e < 4; e++) s[i][e] = 0.f;

            #pragma unroll
            for (int nt = 0; nt < 8; nt++) {
                const int nrow = nt * 8 + (lane & 7);
                #pragma unroll
                for (int kp = 0; kp < 2; kp++) {
                    const int col = kp * 32 + ((lane >> 3) & 3) * 8;
                    const uint32_t off = (uint32_t)(nrow * 72 + col) * 2;
                    uint32_t bh4[4], bl4[4];
                    ldmx4(bh4, stg + SK_H + off);
                    ldmx4(bl4, stg + SK_L + off);
                    mma16816(s[nt], qh[2 * kp],     &bh4[0]);
                    mma16816(s[nt], ql[2 * kp],     &bh4[0]);
                    mma16816(s[nt], qh[2 * kp],     &bl4[0]);
                    mma16816(s[nt], qh[2 * kp + 1], &bh4[2]);
                    mma16816(s[nt], ql[2 * kp + 1], &bh4[2]);
                    mma16816(s[nt], qh[2 * kp + 1], &bl4[2]);
                }
            }

            // ---- causal mask
            const int row0 = qbase + warp * 16 + g;
            const int row1 = row0 + 8;
            #pragma unroll
            for (int nt = 0; nt < 8; nt++) {
                #pragma unroll
                for (int e = 0; e < 2; e++) {
                    const int key = j0 + nt * 8 + tg * 2 + e;
                    if (key > row0) s[nt][e] = -1e30f;
                    if (key > row1) s[nt][2 + e] = -1e30f;
                }
            }

            // ---- online softmax
            float vm0 = -1e30f, vm1 = -1e30f;
            #pragma unroll
            for (int nt = 0; nt < 8; nt++) {
                vm0 = fmaxf(vm0, fmaxf(s[nt][0], s[nt][1]));
                vm1 = fmaxf(vm1, fmaxf(s[nt][2], s[nt][3]));
            }
            vm0 = fmaxf(vm0, __shfl_xor_sync(0xffffffffu, vm0, 1));
            vm0 = fmaxf(vm0, __shfl_xor_sync(0xffffffffu, vm0, 2));
            vm1 = fmaxf(vm1, __shfl_xor_sync(0xffffffffu, vm1, 1));
            vm1 = fmaxf(vm1, __shfl_xor_sync(0xffffffffu, vm1, 2));

            const float nm0 = fmaxf(m0r, vm0), nm1 = fmaxf(m1r, vm1);
            const float corr0 = __expf(m0r - nm0), corr1 = __expf(m1r - nm1);
            m0r = nm0; m1r = nm1;

            float ps0 = 0.f, ps1 = 0.f;
            #pragma unroll
            for (int nt = 0; nt < 8; nt++) {
                s[nt][0] = __expf(s[nt][0] - nm0);
                s[nt][1] = __expf(s[nt][1] - nm0);
                s[nt][2] = __expf(s[nt][2] - nm1);
                s[nt][3] = __expf(s[nt][3] - nm1);
                ps0 += s[nt][0] + s[nt][1];
                ps1 += s[nt][2] + s[nt][3];
            }
            ps0 += __shfl_xor_sync(0xffffffffu, ps0, 1);
            ps0 += __shfl_xor_sync(0xffffffffu, ps0, 2);
            ps1 += __shfl_xor_sync(0xffffffffu, ps1, 1);
            ps1 += __shfl_xor_sync(0xffffffffu, ps1, 2);
            l0s = l0s * corr0 + ps0;
            l1s = l1s * corr1 + ps1;
            #pragma unroll
            for (int nt = 0; nt < 8; nt++) {
                o[nt][0] *= corr0; o[nt][1] *= corr0;
                o[nt][2] *= corr1; o[nt][3] *= corr1;
            }

            // ---- P fragments (C-frag == A-frag layout)
            uint32_t ph[4][4], pl[4][4];
            #pragma unroll
            for (int kt = 0; kt < 4; kt++) {
                split2(s[2 * kt][0],     s[2 * kt][1],     ph[kt][0], pl[kt][0]);
                split2(s[2 * kt][2],     s[2 * kt][3],     ph[kt][1], pl[kt][1]);
                split2(s[2 * kt + 1][0], s[2 * kt + 1][1], ph[kt][2], pl[kt][2]);
                split2(s[2 * kt + 1][2], s[2 * kt + 1][3], ph[kt][3], pl[kt][3]);
            }

            // ---- O += P V
            #pragma unroll
            for (int nt = 0; nt < 8; nt++) {
                const int nrow = nt * 8 + (lane & 7);
                #pragma unroll
                for (int kp = 0; kp < 2; kp++) {
                    const int col = kp * 32 + ((lane >> 3) & 3) * 8;
                    const uint32_t off = (uint32_t)(nrow * 72 + col) * 2;
                    uint32_t vh4[4], vl4[4];
                    ldmx4(vh4, stg + SV_H + off);
                    ldmx4(vl4, stg + SV_L + off);
                    mma16816(o[nt], ph[2 * kp],     &vh4[0]);
                    mma16816(o[nt], pl[2 * kp],     &vh4[0]);
                    mma16816(o[nt], ph[2 * kp],     &vl4[0]);
                    mma16816(o[nt], ph[2 * kp + 1], &vh4[2]);
                    mma16816(o[nt], pl[2 * kp + 1], &vh4[2]);
                    mma16816(o[nt], ph[2 * kp + 1], &vl4[2]);
                }
            }
        }
        __syncthreads();
    }

    // ---- write O as bf16 hi/lo into g_ah/g_al [m][384]
    const float inv0 = 1.f / l0s, inv1 = 1.f / l1s;
    const int row0 = qbase + warp * 16 + g;
    const int row1 = row0 + 8;
    #pragma unroll
    for (int nt = 0; nt < 8; nt++) {
        const int col = h * 64 + nt * 8 + tg * 2;
        uint32_t hi0, lo0, hi1, lo1;
        split2(o[nt][0] * inv0, o[nt][1] * inv0, hi0, lo0);
        split2(o[nt][2] * inv1, o[nt][3] * inv1, hi1, lo1);
        const size_t i0 = (size_t)(b * TT + row0) * CC + col;
        const size_t i1 = (size_t)(b * TT + row1) * CC + col;
        *(uint32_t*)(g_ah + i0) = hi0;  *(uint32_t*)(g_al + i0) = lo0;
        *(uint32_t*)(g_ah + i1) = hi1;  *(uint32_t*)(g_al + i1) = lo1;
    }
}

// ---------------------------------------------------------------------------
extern "C" void kernel_launch(void* const* d_in, const int* in_sizes, int n_in,
                              void* d_out, int out_size)
{
    const float* x  = (const float*)d_in[0];
    const float* Wq = (const float*)d_in[1];
    const float* Wk = (const float*)d_in[2];
    const float* Wv = (const float*)d_in[3];
    const float* Wp = (const float*)d_in[4];
    const float* bp = (const float*)d_in[5];
    float* out = (float*)d_out;

    cudaFuncSetAttribute(gemm_kernel<0>, cudaFuncAttributeMaxDynamicSharedMemorySize, GEMM_SMEM);
    cudaFuncSetAttribute(gemm_kernel<1>, cudaFuncAttributeMaxDynamicSharedMemorySize, GEMM_SMEM);
    cudaFuncSetAttribute(attn_kernel,    cudaFuncAttributeMaxDynamicSharedMemorySize, ATT_SMEM);

    conv_x<<<MTOT * CC / 4 / 256, 256>>>(x);
    conv_w<<<1536 * 384 / 256, 256>>>(Wq, Wk, Wv, Wp);

    __nv_bfloat16 *xh, *xl, *wh, *wl, *ah, *al;
    cudaGetSymbolAddress((void**)&xh, g_xh);
    cudaGetSymbolAddress((void**)&xl, g_xl);
    cudaGetSymbolAddress((void**)&wh, g_wh);
    cudaGetSymbolAddress((void**)&wl, g_wl);
    cudaGetSymbolAddress((void**)&ah, g_ah);
    cudaGetSymbolAddress((void**)&al, g_al);

    dim3 g1(MTOT / 128, 9);
    gemm_kernel<0><<<g1, 256, GEMM_SMEM>>>(xh, xl, wh, wl, nullptr, nullptr);

    attn_kernel<<<BB * HH * 2, 256, ATT_SMEM>>>();

    dim3 g3(MTOT / 128, 3);
    gemm_kernel<1><<<g3, 256, GEMM_SMEM>>>(ah, al, wh + 1152 * 384, wl + 1152 * 384, bp, out);
}

// round 13
// speedup vs baseline: 3.6185x; 1.0013x over previous
#include <cuda_runtime.h>
#include <cuda_bf16.h>
#include <cstdint>

#define BB   128
#define TT   256
#define CC   384
#define HH   6
#define HS   64
#define MTOT (BB*TT)
#define QKV_E 12582912     // = MTOT*CC = BB*HH*TT*HS

// ---------------------------------------------------------------------------
// Pre-split bf16 hi/lo scratch (allocation-free rule: __device__ globals)
// ---------------------------------------------------------------------------
__device__ __nv_bfloat16 g_xh[QKV_E], g_xl[QKV_E];        // x          [m][384]
__device__ __nv_bfloat16 g_qh[QKV_E], g_ql[QKV_E];        // q (scaled) [bh][t][64]
__device__ __nv_bfloat16 g_kh[QKV_E], g_kl[QKV_E];        // k          [bh][t][64]
__device__ __nv_bfloat16 g_vh[QKV_E], g_vl[QKV_E];        // V^T        [bh][d][256]
__device__ __nv_bfloat16 g_ah[QKV_E], g_al[QKV_E];        // attn out   [m][384]
__device__ __nv_bfloat16 g_wh[1536*384], g_wl[1536*384];  // Wall(1152)+Wpt(384), [n][k]

// ---------------------------------------------------------------------------
// helpers
// ---------------------------------------------------------------------------
__device__ __forceinline__ uint32_t smem_u32(const void* p) {
    uint32_t a;
    asm("{ .reg .u64 t; cvta.to.shared.u64 t, %1; cvt.u32.u64 %0, t; }" : "=r"(a) : "l"(p));
    return a;
}
__device__ __forceinline__ void mma16816(float* c, const uint32_t* a, const uint32_t* b) {
    asm volatile(
        "mma.sync.aligned.m16n8k16.row.col.f32.bf16.bf16.f32 "
        "{%0,%1,%2,%3}, {%4,%5,%6,%7}, {%8,%9}, {%0,%1,%2,%3};"
        : "+f"(c[0]), "+f"(c[1]), "+f"(c[2]), "+f"(c[3])
        : "r"(a[0]), "r"(a[1]), "r"(a[2]), "r"(a[3]), "r"(b[0]), "r"(b[1]));
}
__device__ __forceinline__ void ldmx4(uint32_t* r, uint32_t addr) {
    asm volatile("ldmatrix.sync.aligned.m8n8.x4.shared.b16 {%0,%1,%2,%3}, [%4];"
        : "=r"(r[0]), "=r"(r[1]), "=r"(r[2]), "=r"(r[3]) : "r"(addr));
}
#define CP16(dst, src) asm volatile("cp.async.ca.shared.global [%0], [%1], 16;" :: "r"(dst), "l"(src))
#define CP_COMMIT()    asm volatile("cp.async.commit_group;")
#define CP_WAIT(n)     asm volatile("cp.async.wait_group %0;" :: "n"(n))

__device__ __forceinline__ void split2(float a, float b, uint32_t& hi, uint32_t& lo) {
    __nv_bfloat16 ha = __float2bfloat16(a), hb = __float2bfloat16(b);
    __nv_bfloat16 la = __float2bfloat16(a - __bfloat162float(ha));
    __nv_bfloat16 lb = __float2bfloat16(b - __bfloat162float(hb));
    hi = ((uint32_t)__bfloat16_as_ushort(hb) << 16) | __bfloat16_as_ushort(ha);
    lo = ((uint32_t)__bfloat16_as_ushort(lb) << 16) | __bfloat16_as_ushort(la);
}
__device__ __forceinline__ void split1(float a, __nv_bfloat16& h, __nv_bfloat16& l) {
    h = __float2bfloat16(a);
    l = __float2bfloat16(a - __bfloat162float(h));
}

// ---------------------------------------------------------------------------
// convert kernels (one-shot, bandwidth-bound)
// ---------------------------------------------------------------------------
__global__ __launch_bounds__(256) void conv_x(const float* __restrict__ x) {
    const int i = blockIdx.x * 256 + threadIdx.x;     // per float4
    float4 v = ((const float4*)x)[i];
    uint32_t h0, l0, h1, l1;
    split2(v.x, v.y, h0, l0);
    split2(v.z, v.w, h1, l1);
    ((uint32_t*)g_xh)[2 * i] = h0;  ((uint32_t*)g_xh)[2 * i + 1] = h1;
    ((uint32_t*)g_xl)[2 * i] = l0;  ((uint32_t*)g_xl)[2 * i + 1] = l1;
}

__global__ __launch_bounds__(256) void conv_w(
    const float* __restrict__ Wq, const float* __restrict__ Wk,
    const float* __restrict__ Wv, const float* __restrict__ Wp)
{
    const int i = blockIdx.x * 256 + threadIdx.x;     // 1536*384 elements
    const int row = i / 384, k = i % 384;
    float val;
    if (row < 1152) {
        const int t = row / 384, rem = row % 384, h = rem / 64, d = rem % 64;
        const float* W = (t == 0 ? Wq : t == 1 ? Wk : Wv);
        val = W[((size_t)h * 384 + k) * 64 + d];
    } else {
        const int n = row - 1152;
        val = Wp[(size_t)k * 384 + n];
    }
    __nv_bfloat16 hh, ll;
    split1(val, hh, ll);
    g_wh[i] = hh;
    g_wl[i] = ll;
}

// ---------------------------------------------------------------------------
// GEMM: C[128,128] tiles over pre-split bf16. A [m][384], B [n][384].
// 8 warps: wm 0..3 (32 rows), wn 0..1 (64 cols). cp.async double buffer.
// ---------------------------------------------------------------------------
#define GEMM_SMEM 81920

template <int MODE>
__global__ __launch_bounds__(256, 2) void gemm_kernel(
    const __nv_bfloat16* __restrict__ Ah, const __nv_bfloat16* __restrict__ Al,
    const __nv_bfloat16* __restrict__ Bh, const __nv_bfloat16* __restrict__ Bl,
    const float* __restrict__ bp, float* __restrict__ out)
{
    extern __shared__ char sm[];
    const uint32_t sb = smem_u32(sm);

    const int tid  = threadIdx.x;
    const int lane = tid & 31;
    const int warp = tid >> 5;
    const int wm = warp & 3;
    const int wn = warp >> 2;

    const int m0 = blockIdx.x * 128;
    const int n0 = blockIdx.y * 128;

    const int rowL = tid >> 2;
    const int segL = (tid & 3) * 8;
    const uint32_t soBase = (uint32_t)(rowL * 40 + segL) * 2;

    float acc[2][8][4];
    #pragma unroll
    for (int i = 0; i < 2; i++)
        #pragma unroll
        for (int j = 0; j < 8; j++)
            #pragma unroll
            for (int e = 0; e < 4; e++) acc[i][j][e] = 0.f;

    auto issue = [&](int ch, int s) {
        const uint32_t base = sb + s * 40960;
        const int kof = ch * 32 + segL;
        #pragma unroll
        for (int r = 0; r < 2; r++) {
            const int row = rowL + r * 64;
            const uint32_t so = soBase + r * 64 * 80;
            CP16(base +         so, Ah + (size_t)(m0 + row) * 384 + kof);
            CP16(base + 10240 + so, Al + (size_t)(m0 + row) * 384 + kof);
            CP16(base + 20480 + so, Bh + (size_t)(n0 + row) * 384 + kof);
            CP16(base + 30720 + so, Bl + (size_t)(n0 + row) * 384 + kof);
        }
    };

    issue(0, 0);
    CP_COMMIT();

    for (int ch = 0; ch < 12; ch++) {
        if (ch + 1 < 12) { issue(ch + 1, (ch + 1) & 1); CP_COMMIT(); CP_WAIT(1); }
        else             { CP_WAIT(0); }
        __syncthreads();

        const uint32_t sbuf = sb + (ch & 1) * 40960;

        // hoist A fragments for this chunk: [k16][mt]
        uint32_t ah[2][2][4], al[2][2][4];
        #pragma unroll
        for (int k16 = 0; k16 < 2; k16++) {
            #pragma unroll
            for (int mt = 0; mt < 2; mt++) {
                const int row = wm * 32 + mt * 16 + (lane & 15);
                const int col = k16 * 16 + (lane >> 4) * 8;
                const uint32_t off = (uint32_t)(row * 40 + col) * 2;
                ldmx4(ah[k16][mt], sbuf + off);
                ldmx4(al[k16][mt], sbuf + 10240 + off);
            }
        }

        #pragma unroll
        for (int nt = 0; nt < 8; nt++) {
            const int nrow = wn * 64 + nt * 8 + (lane & 7);
            const int col = ((lane >> 3) & 3) * 8;          // 0..24: covers both k16
            const uint32_t off = (uint32_t)(nrow * 40 + col) * 2;
            uint32_t bh4[4], bl4[4];
            ldmx4(bh4, sbuf + 20480 + off);
            ldmx4(bl4, sbuf + 30720 + off);
            #pragma unroll
            for (int k16 = 0; k16 < 2; k16++) {
                #pragma unroll
                for (int mt = 0; mt < 2; mt++) {
                    mma16816(acc[mt][nt], ah[k16][mt], &bh4[2 * k16]);
                    mma16816(acc[mt][nt], al[k16][mt], &bh4[2 * k16]);
                    mma16816(acc[mt][nt], ah[k16][mt], &bl4[2 * k16]);
                }
            }
        }
        __syncthreads();
    }

    // ---- epilogue
    const int g = lane >> 2, tg = lane & 3;
    if (MODE == 0) {
        const int t_sel = blockIdx.y / 3;
        const int h = ((n0 % 384) / 64) + wn;
        if (t_sel == 2) {
            // V: write TRANSPOSED [bh][d][256] bf16 hi/lo
            unsigned short* dh = (unsigned short*)g_vh;
            unsigned short* dl = (unsigned short*)g_vl;
            #pragma unroll
            for (int mt = 0; mt < 2; mt++) {
                #pragma unroll
                for (int rh = 0; rh < 2; rh++) {
                    const int m = m0 + wm * 32 + mt * 16 + g + rh * 8;
                    const int b = m >> 8, t = m & 255;
                    const size_t bhb = (size_t)(b * HH + h) * 64;
                    #pragma unroll
                    for (int nt = 0; nt < 8; nt++) {
                        const int d = nt * 8 + tg * 2;
                        uint32_t hi, lo;
                        split2(acc[mt][nt][rh * 2], acc[mt][nt][rh * 2 + 1], hi, lo);
                        const size_t base = (bhb + d) * 256 + t;
                        dh[base] = (unsigned short)(hi & 0xffff);
                        dh[base + 256] = (unsigned short)(hi >> 16);
                        dl[base] = (unsigned short)(lo & 0xffff);
                        dl[base + 256] = (unsigned short)(lo >> 16);
                    }
                }
            }
        } else {
            __nv_bfloat16 *dh, *dl;
            float scale = 1.f;
            if (t_sel == 0) { dh = g_qh; dl = g_ql; scale = 0.125f; }
            else            { dh = g_kh; dl = g_kl; }
            #pragma unroll
            for (int mt = 0; mt < 2; mt++) {
                #pragma unroll
                for (int rh = 0; rh < 2; rh++) {
                    const int m = m0 + wm * 32 + mt * 16 + g + rh * 8;
                    const int b = m >> 8, t = m & 255;
                    const size_t base = ((size_t)(b * HH + h) * TT + t) * HS;
                    #pragma unroll
                    for (int nt = 0; nt < 8; nt++) {
                        const int d = nt * 8 + tg * 2;
                        uint32_t hi, lo;
                        split2(acc[mt][nt][rh * 2] * scale, acc[mt][nt][rh * 2 + 1] * scale, hi, lo);
                        *(uint32_t*)(dh + base + d) = hi;
                        *(uint32_t*)(dl + base + d) = lo;
                    }
                }
            }
        }
    } else {
        #pragma unroll
        for (int mt = 0; mt < 2; mt++) {
            #pragma unroll
            for (int rh = 0; rh < 2; rh++) {
                const int m = m0 + wm * 32 + mt * 16 + g + rh * 8;
                #pragma unroll
                for (int nt = 0; nt < 8; nt++) {
                    const int n = n0 + wn * 64 + nt * 8 + tg * 2;
                    float2 v = {acc[mt][nt][rh * 2] + bp[n], acc[mt][nt][rh * 2 + 1] + bp[n + 1]};
                    *(float2*)(out + (size_t)m * CC + n) = v;
                }
            }
        }
    }
}

// ---------------------------------------------------------------------------
// Attention: flash-2 mma.sync, pre-split bf16, pre-transposed V.
// Block = (b,h,half): 128 q rows, 8 warps x 16 rows. K/V chunks of 64 keys.
// smem = 2 regions of 36864B. Region0 holds Q during prologue, then becomes
// the odd-parity staging buffer (Q frags are register-resident by then).
// Total 73728B -> 2 CTAs/SM with __launch_bounds__(256,2).
// ---------------------------------------------------------------------------
#define ATT_SMEM 73728
#define SK_H 0
#define SK_L 9216
#define SV_H 18432
#define SV_L 27648

__global__ __launch_bounds__(256, 2) void attn_kernel()
{
    extern __shared__ char sm[];
    const uint32_t sb = smem_u32(sm);

    const int bid = blockIdx.x;
    const int bh = bid >> 1, half = bid & 1;
    const int b = bh / HH, h = bh % HH;
    const int qbase = half * 128;

    const int tid  = threadIdx.x;
    const int lane = tid & 31;
    const int warp = tid >> 5;
    const int g = lane >> 2, tg = lane & 3;

    const int nch = (half == 0) ? 2 : 4;
    const int wmax = qbase + warp * 16 + 15;

    const int srow = tid >> 3;          // 0..31
    const int sseg = (tid & 7) * 8;     // halves

    // stage c: region1 (offset 36864) for even c, region0 (offset 0) for odd c
    auto stage = [&](int c) {
        const uint32_t base = sb + ((c & 1) ? 0u : 36864u);
        const int j0 = c * 64;
        const size_t krow0 = (size_t)bh * TT + j0;
        const size_t vrow0 = (size_t)bh * 64;
        #pragma unroll
        for (int r = 0; r < 2; r++) {
            const int row = srow + r * 32;
            const uint32_t so = (uint32_t)(row * 72 + sseg) * 2;
            CP16(base + SK_H + so, g_kh + (krow0 + row) * HS + sseg);
            CP16(base + SK_L + so, g_kl + (krow0 + row) * HS + sseg);
            CP16(base + SV_H + so, g_vh + (vrow0 + row) * 256 + j0 + sseg);
            CP16(base + SV_L + so, g_vl + (vrow0 + row) * 256 + j0 + sseg);
        }
    };

    // ---- stage Q hi/lo into region0 (offsets 0 / 18432)
    {
        const size_t qrow0 = (size_t)bh * TT + qbase;
        #pragma unroll
        for (int r = 0; r < 4; r++) {
            const int idx = r * 256 + tid;
            const int row = idx >> 3, seg = (idx & 7) * 8;
            const uint32_t so = (uint32_t)(row * 72 + seg) * 2;
            CP16(sb + so, g_qh + (qrow0 + row) * HS + seg);
            CP16(sb + 18432 + so, g_ql + (qrow0 + row) * HS + seg);
        }
        CP_COMMIT();
    }
    stage(0);                 // region1
    CP_COMMIT();
    CP_WAIT(1);               // Q resident; stage0 may still be in flight
    __syncthreads();

    uint32_t qh[4][4], ql[4][4];
    #pragma unroll
    for (int kt = 0; kt < 4; kt++) {
        const int row = warp * 16 + (lane & 15);
        const int col = kt * 16 + (lane >> 4) * 8;
        const uint32_t off = (uint32_t)(row * 72 + col) * 2;
        ldmx4(qh[kt], sb + off);
        ldmx4(ql[kt], sb + 18432 + off);
    }
    __syncthreads();          // all warps done reading Q before region0 is re-staged

    float o[8][4];
    #pragma unroll
    for (int i = 0; i < 8; i++)
        #pragma unroll
        for (int e = 0; e < 4; e++) o[i][e] = 0.f;
    float m0r = -1e30f, m1r = -1e30f, l0s = 0.f, l1s = 0.f;

    for (int c = 0; c < nch; c++) {
        const int j0 = c * 64;
        if (c + 1 < nch) { stage(c + 1); CP_COMMIT(); CP_WAIT(1); }
        else             { CP_WAIT(0); }
        __syncthreads();

        if (j0 <= wmax) {
            const uint32_t stg = sb + ((c & 1) ? 0u : 36864u);

            // ---- S = Q K^T
            float s[8][4];
            #pragma unroll
            for (int i = 0; i < 8; i++)
                #pragma unroll
                for (int e = 0; e < 4; e++) s[i][e] = 0.f;

            #pragma unroll
            for (int nt = 0; nt < 8; nt++) {
                const int nrow = nt * 8 + (lane & 7);
                #pragma unroll
                for (int kp = 0; kp < 2; kp++) {
                    const int col = kp * 32 + ((lane >> 3) & 3) * 8;
                    const uint32_t off = (uint32_t)(nrow * 72 + col) * 2;
                    uint32_t bh4[4], bl4[4];
                    ldmx4(bh4, stg + SK_H + off);
                    ldmx4(bl4, stg + SK_L + off);
                    mma16816(s[nt], qh[2 * kp],     &bh4[0]);
                    mma16816(s[nt], ql[2 * kp],     &bh4[0]);
                    mma16816(s[nt], qh[2 * kp],     &bl4[0]);
                    mma16816(s[nt], qh[2 * kp + 1], &bh4[2]);
                    mma16816(s[nt], ql[2 * kp + 1], &bh4[2]);
                    mma16816(s[nt], qh[2 * kp + 1], &bl4[2]);
                }
            }

            // ---- causal mask
            const int row0 = qbase + warp * 16 + g;
            const int row1 = row0 + 8;
            #pragma unroll
            for (int nt = 0; nt < 8; nt++) {
                #pragma unroll
                for (int e = 0; e < 2; e++) {
                    const int key = j0 + nt * 8 + tg * 2 + e;
                    if (key > row0) s[nt][e] = -1e30f;
                    if (key > row1) s[nt][2 + e] = -1e30f;
                }
            }

            // ---- online softmax
            float vm0 = -1e30f, vm1 = -1e30f;
            #pragma unroll
            for (int nt = 0; nt < 8; nt++) {
                vm0 = fmaxf(vm0, fmaxf(s[nt][0], s[nt][1]));
                vm1 = fmaxf(vm1, fmaxf(s[nt][2], s[nt][3]));
            }
            vm0 = fmaxf(vm0, __shfl_xor_sync(0xffffffffu, vm0, 1));
            vm0 = fmaxf(vm0, __shfl_xor_sync(0xffffffffu, vm0, 2));
            vm1 = fmaxf(vm1, __shfl_xor_sync(0xffffffffu, vm1, 1));
            vm1 = fmaxf(vm1, __shfl_xor_sync(0xffffffffu, vm1, 2));

            const float nm0 = fmaxf(m0r, vm0), nm1 = fmaxf(m1r, vm1);
            const float corr0 = __expf(m0r - nm0), corr1 = __expf(m1r - nm1);
            m0r = nm0; m1r = nm1;

            float ps0 = 0.f, ps1 = 0.f;
            #pragma unroll
            for (int nt = 0; nt < 8; nt++) {
                s[nt][0] = __expf(s[nt][0] - nm0);
                s[nt][1] = __expf(s[nt][1] - nm0);
                s[nt][2] = __expf(s[nt][2] - nm1);
                s[nt][3] = __expf(s[nt][3] - nm1);
                ps0 += s[nt][0] + s[nt][1];
                ps1 += s[nt][2] + s[nt][3];
            }
            ps0 += __shfl_xor_sync(0xffffffffu, ps0, 1);
            ps0 += __shfl_xor_sync(0xffffffffu, ps0, 2);
            ps1 += __shfl_xor_sync(0xffffffffu, ps1, 1);
            ps1 += __shfl_xor_sync(0xffffffffu, ps1, 2);
            l0s = l0s * corr0 + ps0;
            l1s = l1s * corr1 + ps1;
            #pragma unroll
            for (int nt = 0; nt < 8; nt++) {
                o[nt][0] *= corr0; o[nt][1] *= corr0;
                o[nt][2] *= corr1; o[nt][3] *= corr1;
            }

            // ---- O += P V, split by key-half to keep P-frag register load low
            #pragma unroll
            for (int kp = 0; kp < 2; kp++) {
                uint32_t ph[2][4], pl[2][4];
                #pragma unroll
                for (int kt = 0; kt < 2; kt++) {
                    const int s0 = 4 * kp + 2 * kt;
                    split2(s[s0][0],     s[s0][1],     ph[kt][0], pl[kt][0]);
                    split2(s[s0][2],     s[s0][3],     ph[kt][1], pl[kt][1]);
                    split2(s[s0 + 1][0], s[s0 + 1][1], ph[kt][2], pl[kt][2]);
                    split2(s[s0 + 1][2], s[s0 + 1][3], ph[kt][3], pl[kt][3]);
                }
                #pragma unroll
                for (int nt = 0; nt < 8; nt++) {
                    const int nrow = nt * 8 + (lane & 7);
                    const int col = kp * 32 + ((lane >> 3) & 3) * 8;
                    const uint32_t off = (uint32_t)(nrow * 72 + col) * 2;
                    uint32_t vh4[4], vl4[4];
                    ldmx4(vh4, stg + SV_H + off);
                    ldmx4(vl4, stg + SV_L + off);
                    mma16816(o[nt], ph[0], &vh4[0]);
                    mma16816(o[nt], pl[0], &vh4[0]);
                    mma16816(o[nt], ph[0], &vl4[0]);
                    mma16816(o[nt], ph[1], &vh4[2]);
                    mma16816(o[nt], pl[1], &vh4[2]);
                    mma16816(o[nt], ph[1], &vl4[2]);
                }
            }
        }
        __syncthreads();
    }

    // ---- write O as bf16 hi/lo into g_ah/g_al [m][384]
    const float inv0 = 1.f / l0s, inv1 = 1.f / l1s;
    const int row0 = qbase + warp * 16 + g;
    const int row1 = row0 + 8;
    #pragma unroll
    for (int nt = 0; nt < 8; nt++) {
        const int col = h * 64 + nt * 8 + tg * 2;
        uint32_t hi0, lo0, hi1, lo1;
        split2(o[nt][0] * inv0, o[nt][1] * inv0, hi0, lo0);
        split2(o[nt][2] * inv1, o[nt][3] * inv1, hi1, lo1);
        const size_t i0 = (size_t)(b * TT + row0) * CC + col;
        const size_t i1 = (size_t)(b * TT + row1) * CC + col;
        *(uint32_t*)(g_ah + i0) = hi0;  *(uint32_t*)(g_al + i0) = lo0;
        *(uint32_t*)(g_ah + i1) = hi1;  *(uint32_t*)(g_al + i1) = lo1;
    }
}

// ---------------------------------------------------------------------------
extern "C" void kernel_launch(void* const* d_in, const int* in_sizes, int n_in,
                              void* d_out, int out_size)
{
    const float* x  = (const float*)d_in[0];
    const float* Wq = (const float*)d_in[1];
    const float* Wk = (const float*)d_in[2];
    const float* Wv = (const float*)d_in[3];
    const float* Wp = (const float*)d_in[4];
    const float* bp = (const float*)d_in[5];
    float* out = (float*)d_out;

    cudaFuncSetAttribute(gemm_kernel<0>, cudaFuncAttributeMaxDynamicSharedMemorySize, GEMM_SMEM);
    cudaFuncSetAttribute(gemm_kernel<1>, cudaFuncAttributeMaxDynamicSharedMemorySize, GEMM_SMEM);
    cudaFuncSetAttribute(attn_kernel,    cudaFuncAttributeMaxDynamicSharedMemorySize, ATT_SMEM);

    conv_x<<<MTOT * CC / 4 / 256, 256>>>(x);
    conv_w<<<1536 * 384 / 256, 256>>>(Wq, Wk, Wv, Wp);

    __nv_bfloat16 *xh, *xl, *wh, *wl, *ah, *al;
    cudaGetSymbolAddress((void**)&xh, g_xh);
    cudaGetSymbolAddress((void**)&xl, g_xl);
    cudaGetSymbolAddress((void**)&wh, g_wh);
    cudaGetSymbolAddress((void**)&wl, g_wl);
    cudaGetSymbolAddress((void**)&ah, g_ah);
    cudaGetSymbolAddress((void**)&al, g_al);

    dim3 g1(MTOT / 128, 9);
    gemm_kernel<0><<<g1, 256, GEMM_SMEM>>>(xh, xl, wh, wl, nullptr, nullptr);

    attn_kernel<<<BB * HH * 2, 256, ATT_SMEM>>>();

    dim3 g3(MTOT / 128, 3);
    gemm_kernel<1><<<g3, 256, GEMM_SMEM>>>(ah, al, wh + 1152 * 384, wl + 1152 * 384, bp, out);
}

// round 14
// speedup vs baseline: 5.0120x; 1.3851x over previous
#include <cuda_runtime.h>
#include <cuda_fp16.h>
#include <cstdint>

#define BB   128
#define TT   256
#define CC   384
#define HH   6
#define HS   64
#define MTOT (BB*TT)
#define QKV_E 12582912     // = MTOT*CC = BB*HH*TT*HS

// ---------------------------------------------------------------------------
// fp16 scratch (allocation-free rule: __device__ globals)
// Activations: single fp16. Stationary operands: fp16 hi + lo.
// ---------------------------------------------------------------------------
__device__ __half g_x16[QKV_E];                      // x        [m][384]
__device__ __half g_q16[QKV_E];                      // q*0.125  [bh][t][64]
__device__ __half g_kh[QKV_E], g_kl[QKV_E];          // k        [bh][t][64]
__device__ __half g_vh[QKV_E], g_vl[QKV_E];          // V^T      [bh][d][256]
__device__ __half g_a16[QKV_E];                      // attn out [m][384]
__device__ __half g_wh[1536*384], g_wl[1536*384];    // Wall(1152)+Wpt(384), [n][k]

// ---------------------------------------------------------------------------
// helpers
// ---------------------------------------------------------------------------
__device__ __forceinline__ uint32_t smem_u32(const void* p) {
    uint32_t a;
    asm("{ .reg .u64 t; cvta.to.shared.u64 t, %1; cvt.u32.u64 %0, t; }" : "=r"(a) : "l"(p));
    return a;
}
__device__ __forceinline__ void mma16816(float* c, const uint32_t* a, const uint32_t* b) {
    asm volatile(
        "mma.sync.aligned.m16n8k16.row.col.f32.f16.f16.f32 "
        "{%0,%1,%2,%3}, {%4,%5,%6,%7}, {%8,%9}, {%0,%1,%2,%3};"
        : "+f"(c[0]), "+f"(c[1]), "+f"(c[2]), "+f"(c[3])
        : "r"(a[0]), "r"(a[1]), "r"(a[2]), "r"(a[3]), "r"(b[0]), "r"(b[1]));
}
__device__ __forceinline__ void ldmx4(uint32_t* r, uint32_t addr) {
    asm volatile("ldmatrix.sync.aligned.m8n8.x4.shared.b16 {%0,%1,%2,%3}, [%4];"
        : "=r"(r[0]), "=r"(r[1]), "=r"(r[2]), "=r"(r[3]) : "r"(addr));
}
#define CP16(dst, src) asm volatile("cp.async.ca.shared.global [%0], [%1], 16;" :: "r"(dst), "l"(src))
#define CP_COMMIT()    asm volatile("cp.async.commit_group;")
#define CP_WAIT(n)     asm volatile("cp.async.wait_group %0;" :: "n"(n))

__device__ __forceinline__ uint32_t hpack2(float a, float b) {
    __half2 h = __floats2half2_rn(a, b);      // a -> low half
    return reinterpret_cast<uint32_t&>(h);
}
__device__ __forceinline__ void hsplit2(float a, float b, uint32_t& hi, uint32_t& lo) {
    const float ha = __half2float(__float2half_rn(a));
    const float hb = __half2float(__float2half_rn(b));
    hi = hpack2(ha, hb);
    lo = hpack2(a - ha, b - hb);
}
__device__ __forceinline__ void hsplit1(float a, __half& h, __half& l) {
    h = __float2half_rn(a);
    l = __float2half_rn(a - __half2float(h));
}

// ---------------------------------------------------------------------------
// convert kernels (one-shot, bandwidth-bound)
// ---------------------------------------------------------------------------
__global__ __launch_bounds__(256) void conv_x(const float* __restrict__ x) {
    const int i = blockIdx.x * 256 + threadIdx.x;     // per float4
    float4 v = ((const float4*)x)[i];
    uint2 p;
    p.x = hpack2(v.x, v.y);
    p.y = hpack2(v.z, v.w);
    ((uint2*)g_x16)[i] = p;
}

__global__ __launch_bounds__(256) void conv_w(
    const float* __restrict__ Wq, const float* __restrict__ Wk,
    const float* __restrict__ Wv, const float* __restrict__ Wp)
{
    const int i = blockIdx.x * 256 + threadIdx.x;     // 1536*384 elements
    const int row = i / 384, k = i % 384;
    float val;
    if (row < 1152) {
        const int t = row / 384, rem = row % 384, h = rem / 64, d = rem % 64;
        const float* W = (t == 0 ? Wq : t == 1 ? Wk : Wv);
        val = W[((size_t)h * 384 + k) * 64 + d];
    } else {
        const int n = row - 1152;
        val = Wp[(size_t)k * 384 + n];
    }
    __half hh, ll;
    hsplit1(val, hh, ll);
    g_wh[i] = hh;
    g_wl[i] = ll;
}

// ---------------------------------------------------------------------------
// GEMM: C[128,128] tiles. A single fp16 [m][384]; B split fp16 [n][384].
// 8 warps: wm 0..3 (32 rows), wn 0..1 (64 cols). cp.async double buffer.
// stage: A 0 (10240B), BH 10240, BL 20480 -> 30720B/stage, 2 stages = 61440
// ---------------------------------------------------------------------------
#define GEMM_SMEM 61440

template <int MODE>
__global__ __launch_bounds__(256, 2) void gemm_kernel(
    const __half* __restrict__ A16,
    const __half* __restrict__ Bh, const __half* __restrict__ Bl,
    const float* __restrict__ bp, float* __restrict__ out)
{
    extern __shared__ char sm[];
    const uint32_t sb = smem_u32(sm);

    const int tid  = threadIdx.x;
    const int lane = tid & 31;
    const int warp = tid >> 5;
    const int wm = warp & 3;
    const int wn = warp >> 2;

    const int m0 = blockIdx.x * 128;
    const int n0 = blockIdx.y * 128;

    const int rowL = tid >> 2;             // 0..63 (+64 second pass)
    const int segL = (tid & 3) * 8;        // halves
    const uint32_t soBase = (uint32_t)(rowL * 40 + segL) * 2;

    float acc[2][8][4];
    #pragma unroll
    for (int i = 0; i < 2; i++)
        #pragma unroll
        for (int j = 0; j < 8; j++)
            #pragma unroll
            for (int e = 0; e < 4; e++) acc[i][j][e] = 0.f;

    auto issue = [&](int ch, int s) {
        const uint32_t base = sb + s * 30720;
        const int kof = ch * 32 + segL;
        #pragma unroll
        for (int r = 0; r < 2; r++) {
            const int row = rowL + r * 64;
            const uint32_t so = soBase + r * 64 * 80;
            CP16(base +         so, A16 + (size_t)(m0 + row) * 384 + kof);
            CP16(base + 10240 + so, Bh  + (size_t)(n0 + row) * 384 + kof);
            CP16(base + 20480 + so, Bl  + (size_t)(n0 + row) * 384 + kof);
        }
    };

    issue(0, 0);
    CP_COMMIT();

    for (int ch = 0; ch < 12; ch++) {
        if (ch + 1 < 12) { issue(ch + 1, (ch + 1) & 1); CP_COMMIT(); CP_WAIT(1); }
        else             { CP_WAIT(0); }
        __syncthreads();

        const uint32_t sbuf = sb + (ch & 1) * 30720;

        // hoist A fragments for this chunk: [k16][mt]
        uint32_t ah[2][2][4];
        #pragma unroll
        for (int k16 = 0; k16 < 2; k16++) {
            #pragma unroll
            for (int mt = 0; mt < 2; mt++) {
                const int row = wm * 32 + mt * 16 + (lane & 15);
                const int col = k16 * 16 + (lane >> 4) * 8;
                const uint32_t off = (uint32_t)(row * 40 + col) * 2;
                ldmx4(ah[k16][mt], sbuf + off);
            }
        }

        #pragma unroll
        for (int nt = 0; nt < 8; nt++) {
            const int nrow = wn * 64 + nt * 8 + (lane & 7);
            const int col = ((lane >> 3) & 3) * 8;          // covers both k16
            const uint32_t off = (uint32_t)(nrow * 40 + col) * 2;
            uint32_t bh4[4], bl4[4];
            ldmx4(bh4, sbuf + 10240 + off);
            ldmx4(bl4, sbuf + 20480 + off);
            #pragma unroll
            for (int k16 = 0; k16 < 2; k16++) {
                #pragma unroll
                for (int mt = 0; mt < 2; mt++) {
                    mma16816(acc[mt][nt], ah[k16][mt], &bh4[2 * k16]);
                    mma16816(acc[mt][nt], ah[k16][mt], &bl4[2 * k16]);
                }
            }
        }
        __syncthreads();
    }

    // ---- epilogue
    const int g = lane >> 2, tg = lane & 3;
    if (MODE == 0) {
        const int t_sel = blockIdx.y / 3;
        const int h = ((n0 % 384) / 64) + wn;
        if (t_sel == 2) {
            // V: write TRANSPOSED [bh][d][256] fp16 hi/lo
            unsigned short* dh = (unsigned short*)g_vh;
            unsigned short* dl = (unsigned short*)g_vl;
            #pragma unroll
            for (int mt = 0; mt < 2; mt++) {
                #pragma unroll
                for (int rh = 0; rh < 2; rh++) {
                    const int m = m0 + wm * 32 + mt * 16 + g + rh * 8;
                    const int b = m >> 8, t = m & 255;
                    const size_t bhb = (size_t)(b * HH + h) * 64;
                    #pragma unroll
                    for (int nt = 0; nt < 8; nt++) {
                        const int d = nt * 8 + tg * 2;
                        uint32_t hi, lo;
                        hsplit2(acc[mt][nt][rh * 2], acc[mt][nt][rh * 2 + 1], hi, lo);
                        const size_t base = (bhb + d) * 256 + t;
                        dh[base] = (unsigned short)(hi & 0xffff);
                        dh[base + 256] = (unsigned short)(hi >> 16);
                        dl[base] = (unsigned short)(lo & 0xffff);
                        dl[base + 256] = (unsigned short)(lo >> 16);
                    }
                }
            }
        } else if (t_sel == 0) {
            // Q: single fp16, scaled by 1/8
            #pragma unroll
            for (int mt = 0; mt < 2; mt++) {
                #pragma unroll
                for (int rh = 0; rh < 2; rh++) {
                    const int m = m0 + wm * 32 + mt * 16 + g + rh * 8;
                    const int b = m >> 8, t = m & 255;
                    const size_t base = ((size_t)(b * HH + h) * TT + t) * HS;
                    #pragma unroll
                    for (int nt = 0; nt < 8; nt++) {
                        const int d = nt * 8 + tg * 2;
                        *(uint32_t*)(g_q16 + base + d) =
                            hpack2(acc[mt][nt][rh * 2] * 0.125f, acc[mt][nt][rh * 2 + 1] * 0.125f);
                    }
                }
            }
        } else {
            // K: fp16 hi/lo
            #pragma unroll
            for (int mt = 0; mt < 2; mt++) {
                #pragma unroll
                for (int rh = 0; rh < 2; rh++) {
                    const int m = m0 + wm * 32 + mt * 16 + g + rh * 8;
                    const int b = m >> 8, t = m & 255;
                    const size_t base = ((size_t)(b * HH + h) * TT + t) * HS;
                    #pragma unroll
                    for (int nt = 0; nt < 8; nt++) {
                        const int d = nt * 8 + tg * 2;
                        uint32_t hi, lo;
                        hsplit2(acc[mt][nt][rh * 2], acc[mt][nt][rh * 2 + 1], hi, lo);
                        *(uint32_t*)(g_kh + base + d) = hi;
                        *(uint32_t*)(g_kl + base + d) = lo;
                    }
                }
            }
        }
    } else {
        #pragma unroll
        for (int mt = 0; mt < 2; mt++) {
            #pragma unroll
            for (int rh = 0; rh < 2; rh++) {
                const int m = m0 + wm * 32 + mt * 16 + g + rh * 8;
                #pragma unroll
                for (int nt = 0; nt < 8; nt++) {
                    const int n = n0 + wn * 64 + nt * 8 + tg * 2;
                    float2 v = {acc[mt][nt][rh * 2] + bp[n], acc[mt][nt][rh * 2 + 1] + bp[n + 1]};
                    *(float2*)(out + (size_t)m * CC + n) = v;
                }
            }
        }
    }
}

// ---------------------------------------------------------------------------
// Attention: flash-2 mma.sync, fp16 2-term (Q/P single, K/V split).
// Block = (b,h,half): 128 q rows, 8 warps x 16 rows. K/V chunks of 64 keys.
// smem = 2 regions of 36864B (KH,KL,VH,VL @ 9216 each). Region0 holds Q
// (18432B single fp16) during the prologue only. Total 73728 -> 2 CTAs/SM.
// ---------------------------------------------------------------------------
#define ATT_SMEM 73728
#define SK_H 0
#define SK_L 9216
#define SV_H 18432
#define SV_L 27648

__global__ __launch_bounds__(256, 2) void attn_kernel()
{
    extern __shared__ char sm[];
    const uint32_t sb = smem_u32(sm);

    const int bid = blockIdx.x;
    const int bh = bid >> 1, half = bid & 1;
    const int b = bh / HH, h = bh % HH;
    const int qbase = half * 128;

    const int tid  = threadIdx.x;
    const int lane = tid & 31;
    const int warp = tid >> 5;
    const int g = lane >> 2, tg = lane & 3;

    const int nch = (half == 0) ? 2 : 4;
    const int wmax = qbase + warp * 16 + 15;

    const int srow = tid >> 3;          // 0..31
    const int sseg = (tid & 7) * 8;     // halves

    // stage c: region1 (offset 36864) for even c, region0 (offset 0) for odd c
    auto stage = [&](int c) {
        const uint32_t base = sb + ((c & 1) ? 0u : 36864u);
        const int j0 = c * 64;
        const size_t krow0 = (size_t)bh * TT + j0;
        const size_t vrow0 = (size_t)bh * 64;
        #pragma unroll
        for (int r = 0; r < 2; r++) {
            const int row = srow + r * 32;
            const uint32_t so = (uint32_t)(row * 72 + sseg) * 2;
            CP16(base + SK_H + so, g_kh + (krow0 + row) * HS + sseg);
            CP16(base + SK_L + so, g_kl + (krow0 + row) * HS + sseg);
            CP16(base + SV_H + so, g_vh + (vrow0 + row) * 256 + j0 + sseg);
            CP16(base + SV_L + so, g_vl + (vrow0 + row) * 256 + j0 + sseg);
        }
    };

    // ---- stage Q (single fp16, pre-scaled) into region0
    {
        const size_t qrow0 = (size_t)bh * TT + qbase;
        #pragma unroll
        for (int r = 0; r < 4; r++) {
            const int idx = r * 256 + tid;
            const int row = idx >> 3, seg = (idx & 7) * 8;
            const uint32_t so = (uint32_t)(row * 72 + seg) * 2;
            CP16(sb + so, g_q16 + (qrow0 + row) * HS + seg);
        }
        CP_COMMIT();
    }
    stage(0);                 // region1
    CP_COMMIT();
    CP_WAIT(1);               // Q resident; stage0 may still be in flight
    __syncthreads();

    uint32_t qh[4][4];
    #pragma unroll
    for (int kt = 0; kt < 4; kt++) {
        const int row = warp * 16 + (lane & 15);
        const int col = kt * 16 + (lane >> 4) * 8;
        const uint32_t off = (uint32_t)(row * 72 + col) * 2;
        ldmx4(qh[kt], sb + off);
    }
    __syncthreads();          // all warps done reading Q before region0 is re-staged

    float o[8][4];
    #pragma unroll
    for (int i = 0; i < 8; i++)
        #pragma unroll
        for (int e = 0; e < 4; e++) o[i][e] = 0.f;
    float m0r = -1e30f, m1r = -1e30f, l0s = 0.f, l1s = 0.f;

    for (int c = 0; c < nch; c++) {
        const int j0 = c * 64;
        if (c + 1 < nch) { stage(c + 1); CP_COMMIT(); CP_WAIT(1); }
        else             { CP_WAIT(0); }
        __syncthreads();

        if (j0 <= wmax) {
            const uint32_t stg = sb + ((c & 1) ? 0u : 36864u);

            // ---- S = Q K^T  (Q single, K 2-term)
            float s[8][4];
            #pragma unroll
            for (int i = 0; i < 8; i++)
                #pragma unroll
                for (int e = 0; e < 4; e++) s[i][e] = 0.f;

            #pragma unroll
            for (int nt = 0; nt < 8; nt++) {
                const int nrow = nt * 8 + (lane & 7);
                #pragma unroll
                for (int kp = 0; kp < 2; kp++) {
                    const int col = kp * 32 + ((lane >> 3) & 3) * 8;
                    const uint32_t off = (uint32_t)(nrow * 72 + col) * 2;
                    uint32_t kh4[4], kl4[4];
                    ldmx4(kh4, stg + SK_H + off);
                    ldmx4(kl4, stg + SK_L + off);
                    mma16816(s[nt], qh[2 * kp],     &kh4[0]);
                    mma16816(s[nt], qh[2 * kp],     &kl4[0]);
                    mma16816(s[nt], qh[2 * kp + 1], &kh4[2]);
                    mma16816(s[nt], qh[2 * kp + 1], &kl4[2]);
                }
            }

            // ---- causal mask
            const int row0 = qbase + warp * 16 + g;
            const int row1 = row0 + 8;
            #pragma unroll
            for (int nt = 0; nt < 8; nt++) {
                #pragma unroll
                for (int e = 0; e < 2; e++) {
                    const int key = j0 + nt * 8 + tg * 2 + e;
                    if (key > row0) s[nt][e] = -1e30f;
                    if (key > row1) s[nt][2 + e] = -1e30f;
                }
            }

            // ---- online softmax
            float vm0 = -1e30f, vm1 = -1e30f;
            #pragma unroll
            for (int nt = 0; nt < 8; nt++) {
                vm0 = fmaxf(vm0, fmaxf(s[nt][0], s[nt][1]));
                vm1 = fmaxf(vm1, fmaxf(s[nt][2], s[nt][3]));
            }
            vm0 = fmaxf(vm0, __shfl_xor_sync(0xffffffffu, vm0, 1));
            vm0 = fmaxf(vm0, __shfl_xor_sync(0xffffffffu, vm0, 2));
            vm1 = fmaxf(vm1, __shfl_xor_sync(0xffffffffu, vm1, 1));
            vm1 = fmaxf(vm1, __shfl_xor_sync(0xffffffffu, vm1, 2));

            const float nm0 = fmaxf(m0r, vm0), nm1 = fmaxf(m1r, vm1);
            const float corr0 = __expf(m0r - nm0), corr1 = __expf(m1r - nm1);
            m0r = nm0; m1r = nm1;

            float ps0 = 0.f, ps1 = 0.f;
            #pragma unroll
            for (int nt = 0; nt < 8; nt++) {
                s[nt][0] = __expf(s[nt][0] - nm0);
                s[nt][1] = __expf(s[nt][1] - nm0);
                s[nt][2] = __expf(s[nt][2] - nm1);
                s[nt][3] = __expf(s[nt][3] - nm1);
                ps0 += s[nt][0] + s[nt][1];
                ps1 += s[nt][2] + s[nt][3];
            }
            ps0 += __shfl_xor_sync(0xffffffffu, ps0, 1);
            ps0 += __shfl_xor_sync(0xffffffffu, ps0, 2);
            ps1 += __shfl_xor_sync(0xffffffffu, ps1, 1);
            ps1 += __shfl_xor_sync(0xffffffffu, ps1, 2);
            l0s = l0s * corr0 + ps0;
            l1s = l1s * corr1 + ps1;
            #pragma unroll
            for (int nt = 0; nt < 8; nt++) {
                o[nt][0] *= corr0; o[nt][1] *= corr0;
                o[nt][2] *= corr1; o[nt][3] *= corr1;
            }

            // ---- O += P V  (P single fp16, V 2-term), by key-half
            #pragma unroll
            for (int kp = 0; kp < 2; kp++) {
                uint32_t ph[2][4];
                #pragma unroll
                for (int kt = 0; kt < 2; kt++) {
                    const int s0 = 4 * kp + 2 * kt;
                    ph[kt][0] = hpack2(s[s0][0],     s[s0][1]);
                    ph[kt][1] = hpack2(s[s0][2],     s[s0][3]);
                    ph[kt][2] = hpack2(s[s0 + 1][0], s[s0 + 1][1]);
                    ph[kt][3] = hpack2(s[s0 + 1][2], s[s0 + 1][3]);
                }
                #pragma unroll
                for (int nt = 0; nt < 8; nt++) {
                    const int nrow = nt * 8 + (lane & 7);
                    const int col = kp * 32 + ((lane >> 3) & 3) * 8;
                    const uint32_t off = (uint32_t)(nrow * 72 + col) * 2;
                    uint32_t vh4[4], vl4[4];
                    ldmx4(vh4, stg + SV_H + off);
                    ldmx4(vl4, stg + SV_L + off);
                    mma16816(o[nt], ph[0], &vh4[0]);
                    mma16816(o[nt], ph[0], &vl4[0]);
                    mma16816(o[nt], ph[1], &vh4[2]);
                    mma16816(o[nt], ph[1], &vl4[2]);
                }
            }
        }
        __syncthreads();
    }

    // ---- write O as single fp16 into g_a16 [m][384]
    const float inv0 = 1.f / l0s, inv1 = 1.f / l1s;
    const int row0 = qbase + warp * 16 + g;
    const int row1 = row0 + 8;
    #pragma unroll
    for (int nt = 0; nt < 8; nt++) {
        const int col = h * 64 + nt * 8 + tg * 2;
        const size_t i0 = (size_t)(b * TT + row0) * CC + col;
        const size_t i1 = (size_t)(b * TT + row1) * CC + col;
        *(uint32_t*)(g_a16 + i0) = hpack2(o[nt][0] * inv0, o[nt][1] * inv0);
        *(uint32_t*)(g_a16 + i1) = hpack2(o[nt][2] * inv1, o[nt][3] * inv1);
    }
}

// ---------------------------------------------------------------------------
extern "C" void kernel_launch(void* const* d_in, const int* in_sizes, int n_in,
                              void* d_out, int out_size)
{
    const float* x  = (const float*)d_in[0];
    const float* Wq = (const float*)d_in[1];
    const float* Wk = (const float*)d_in[2];
    const float* Wv = (const float*)d_in[3];
    const float* Wp = (const float*)d_in[4];
    const float* bp = (const float*)d_in[5];
    float* out = (float*)d_out;

    cudaFuncSetAttribute(gemm_kernel<0>, cudaFuncAttributeMaxDynamicSharedMemorySize, GEMM_SMEM);
    cudaFuncSetAttribute(gemm_kernel<1>, cudaFuncAttributeMaxDynamicSharedMemorySize, GEMM_SMEM);
    cudaFuncSetAttribute(attn_kernel,    cudaFuncAttributeMaxDynamicSharedMemorySize, ATT_SMEM);

    conv_x<<<MTOT * CC / 4 / 256, 256>>>(x);
    conv_w<<<1536 * 384 / 256, 256>>>(Wq, Wk, Wv, Wp);

    __half *x16, *wh, *wl, *a16;
    cudaGetSymbolAddress((void**)&x16, g_x16);
    cudaGetSymbolAddress((void**)&wh,  g_wh);
    cudaGetSymbolAddress((void**)&wl,  g_wl);
    cudaGetSymbolAddress((void**)&a16, g_a16);

    dim3 g1(MTOT / 128, 9);
    gemm_kernel<0><<<g1, 256, GEMM_SMEM>>>(x16, wh, wl, nullptr, nullptr);

    attn_kernel<<<BB * HH * 2, 256, ATT_SMEM>>>();

    dim3 g3(MTOT / 128, 3);
    gemm_kernel<1><<<g3, 256, GEMM_SMEM>>>(a16, wh + 1152 * 384, wl + 1152 * 384, bp, out);
}

// round 15
// speedup vs baseline: 5.0622x; 1.0100x over previous
#include <cuda_runtime.h>
#include <cuda_fp16.h>
#include <cstdint>

#define BB   128
#define TT   256
#define CC   384
#define HH   6
#define HS   64
#define MTOT (BB*TT)
#define QKV_E 12582912     // = MTOT*CC = BB*HH*TT*HS

// ---------------------------------------------------------------------------
// fp16 scratch (allocation-free rule: __device__ globals)
// Activations: single fp16. Stationary operands: fp16 hi + lo.
// ---------------------------------------------------------------------------
__device__ __half g_x16[QKV_E];                      // x        [m][384]
__device__ __half g_q16[QKV_E];                      // q*0.125  [bh][t][64]
__device__ __half g_kh[QKV_E], g_kl[QKV_E];          // k        [bh][t][64]
__device__ __half g_vh[QKV_E], g_vl[QKV_E];          // V^T      [bh][d][256]
__device__ __half g_a16[QKV_E];                      // attn out [m][384]
__device__ __half g_wh[1536*384], g_wl[1536*384];    // Wall(1152)+Wpt(384), [n][k]

// ---------------------------------------------------------------------------
// helpers
// ---------------------------------------------------------------------------
__device__ __forceinline__ uint32_t smem_u32(const void* p) {
    uint32_t a;
    asm("{ .reg .u64 t; cvta.to.shared.u64 t, %1; cvt.u32.u64 %0, t; }" : "=r"(a) : "l"(p));
    return a;
}
__device__ __forceinline__ void mma16816(float* c, const uint32_t* a, const uint32_t* b) {
    asm volatile(
        "mma.sync.aligned.m16n8k16.row.col.f32.f16.f16.f32 "
        "{%0,%1,%2,%3}, {%4,%5,%6,%7}, {%8,%9}, {%0,%1,%2,%3};"
        : "+f"(c[0]), "+f"(c[1]), "+f"(c[2]), "+f"(c[3])
        : "r"(a[0]), "r"(a[1]), "r"(a[2]), "r"(a[3]), "r"(b[0]), "r"(b[1]));
}
__device__ __forceinline__ void ldmx4(uint32_t* r, uint32_t addr) {
    asm volatile("ldmatrix.sync.aligned.m8n8.x4.shared.b16 {%0,%1,%2,%3}, [%4];"
        : "=r"(r[0]), "=r"(r[1]), "=r"(r[2]), "=r"(r[3]) : "r"(addr));
}
#define CP16(dst, src) asm volatile("cp.async.ca.shared.global [%0], [%1], 16;" :: "r"(dst), "l"(src))
#define CP_COMMIT()    asm volatile("cp.async.commit_group;")
#define CP_WAIT(n)     asm volatile("cp.async.wait_group %0;" :: "n"(n))

__device__ __forceinline__ uint32_t hpack2(float a, float b) {
    __half2 h = __floats2half2_rn(a, b);      // a -> low half
    return reinterpret_cast<uint32_t&>(h);
}
__device__ __forceinline__ void hsplit2(float a, float b, uint32_t& hi, uint32_t& lo) {
    const float ha = __half2float(__float2half_rn(a));
    const float hb = __half2float(__float2half_rn(b));
    hi = hpack2(ha, hb);
    lo = hpack2(a - ha, b - hb);
}
__device__ __forceinline__ void hsplit1(float a, __half& h, __half& l) {
    h = __float2half_rn(a);
    l = __float2half_rn(a - __half2float(h));
}

// ---------------------------------------------------------------------------
// merged convert kernel (one-shot, bandwidth-bound)
// blocks [0, 12288): x -> fp16.  blocks [12288, 14592): weights -> fp16 hi/lo
// ---------------------------------------------------------------------------
#define CONV_XBLK 12288
#define CONV_WBLK 2304

__global__ __launch_bounds__(256) void conv_all(
    const float* __restrict__ x,
    const float* __restrict__ Wq, const float* __restrict__ Wk,
    const float* __restrict__ Wv, const float* __restrict__ Wp)
{
    if (blockIdx.x < CONV_XBLK) {
        const int i = blockIdx.x * 256 + threadIdx.x;     // per float4
        float4 v = ((const float4*)x)[i];
        uint2 p;
        p.x = hpack2(v.x, v.y);
        p.y = hpack2(v.z, v.w);
        ((uint2*)g_x16)[i] = p;
    } else {
        const int i = (blockIdx.x - CONV_XBLK) * 256 + threadIdx.x;   // 1536*384
        const int row = i / 384, k = i % 384;
        float val;
        if (row < 1152) {
            const int t = row / 384, rem = row % 384, h = rem / 64, d = rem % 64;
            const float* W = (t == 0 ? Wq : t == 1 ? Wk : Wv);
            val = W[((size_t)h * 384 + k) * 64 + d];
        } else {
            const int n = row - 1152;
            val = Wp[(size_t)k * 384 + n];
        }
        __half hh, ll;
        hsplit1(val, hh, ll);
        g_wh[i] = hh;
        g_wl[i] = ll;
    }
}

// ---------------------------------------------------------------------------
// GEMM: C[128,128] tiles. A single fp16 [m][384]; B split fp16 [n][384].
// 8 warps: wm 0..3 (32 rows), wn 0..1 (64 cols).
// 3-stage cp.async rotation, ONE __syncthreads per k-chunk.
// stage: A 0 (10240B), BH 10240, BL 20480 -> 30720B; 3 stages = 92160
// ---------------------------------------------------------------------------
#define GEMM_SMEM 92160

template <int MODE>
__global__ __launch_bounds__(256, 2) void gemm_kernel(
    const __half* __restrict__ A16,
    const __half* __restrict__ Bh, const __half* __restrict__ Bl,
    const float* __restrict__ bp, float* __restrict__ out)
{
    extern __shared__ char sm[];
    const uint32_t sb = smem_u32(sm);

    const int tid  = threadIdx.x;
    const int lane = tid & 31;
    const int warp = tid >> 5;
    const int wm = warp & 3;
    const int wn = warp >> 2;

    const int m0 = blockIdx.x * 128;
    const int n0 = blockIdx.y * 128;

    const int rowL = tid >> 2;             // 0..63 (+64 second pass)
    const int segL = (tid & 3) * 8;        // halves
    const uint32_t soBase = (uint32_t)(rowL * 40 + segL) * 2;

    float acc[2][8][4];
    #pragma unroll
    for (int i = 0; i < 2; i++)
        #pragma unroll
        for (int j = 0; j < 8; j++)
            #pragma unroll
            for (int e = 0; e < 4; e++) acc[i][j][e] = 0.f;

    auto issue = [&](int ch, int s) {
        const uint32_t base = sb + s * 30720;
        const int kof = ch * 32 + segL;
        #pragma unroll
        for (int r = 0; r < 2; r++) {
            const int row = rowL + r * 64;
            const uint32_t so = soBase + r * 64 * 80;
            CP16(base +         so, A16 + (size_t)(m0 + row) * 384 + kof);
            CP16(base + 10240 + so, Bh  + (size_t)(n0 + row) * 384 + kof);
            CP16(base + 20480 + so, Bl  + (size_t)(n0 + row) * 384 + kof);
        }
    };

    issue(0, 0); CP_COMMIT();
    issue(1, 1); CP_COMMIT();

    int sc = 0;                 // ch % 3
    int si = 2;                 // (ch+2) % 3
    for (int ch = 0; ch < 12; ch++) {
        if (ch < 11) { CP_WAIT(1); }      // load ch complete (ch+1 may be pending)
        else         { CP_WAIT(0); }
        __syncthreads();                  // also retires reads of buffer si (iter ch-1)
        if (ch + 2 < 12) { issue(ch + 2, si); CP_COMMIT(); }

        const uint32_t sbuf = sb + sc * 30720;

        // hoist A fragments for this chunk: [k16][mt]
        uint32_t ah[2][2][4];
        #pragma unroll
        for (int k16 = 0; k16 < 2; k16++) {
            #pragma unroll
            for (int mt = 0; mt < 2; mt++) {
                const int row = wm * 32 + mt * 16 + (lane & 15);
                const int col = k16 * 16 + (lane >> 4) * 8;
                const uint32_t off = (uint32_t)(row * 40 + col) * 2;
                ldmx4(ah[k16][mt], sbuf + off);
            }
        }

        #pragma unroll
        for (int nt = 0; nt < 8; nt++) {
            const int nrow = wn * 64 + nt * 8 + (lane & 7);
            const int col = ((lane >> 3) & 3) * 8;          // covers both k16
            const uint32_t off = (uint32_t)(nrow * 40 + col) * 2;
            uint32_t bh4[4], bl4[4];
            ldmx4(bh4, sbuf + 10240 + off);
            ldmx4(bl4, sbuf + 20480 + off);
            #pragma unroll
            for (int k16 = 0; k16 < 2; k16++) {
                #pragma unroll
                for (int mt = 0; mt < 2; mt++) {
                    mma16816(acc[mt][nt], ah[k16][mt], &bh4[2 * k16]);
                    mma16816(acc[mt][nt], ah[k16][mt], &bl4[2 * k16]);
                }
            }
        }
        sc = (sc == 2) ? 0 : sc + 1;
        si = (si == 2) ? 0 : si + 1;
    }

    // ---- epilogue
    const int g = lane >> 2, tg = lane & 3;
    if (MODE == 0) {
        const int t_sel = blockIdx.y / 3;
        const int h = ((n0 % 384) / 64) + wn;
        if (t_sel == 2) {
            // V: write TRANSPOSED [bh][d][256] fp16 hi/lo
            unsigned short* dh = (unsigned short*)g_vh;
            unsigned short* dl = (unsigned short*)g_vl;
            #pragma unroll
            for (int mt = 0; mt < 2; mt++) {
                #pragma unroll
                for (int rh = 0; rh < 2; rh++) {
                    const int m = m0 + wm * 32 + mt * 16 + g + rh * 8;
                    const int b = m >> 8, t = m & 255;
                    const size_t bhb = (size_t)(b * HH + h) * 64;
                    #pragma unroll
                    for (int nt = 0; nt < 8; nt++) {
                        const int d = nt * 8 + tg * 2;
                        uint32_t hi, lo;
                        hsplit2(acc[mt][nt][rh * 2], acc[mt][nt][rh * 2 + 1], hi, lo);
                        const size_t base = (bhb + d) * 256 + t;
                        dh[base] = (unsigned short)(hi & 0xffff);
                        dh[base + 256] = (unsigned short)(hi >> 16);
                        dl[base] = (unsigned short)(lo & 0xffff);
                        dl[base + 256] = (unsigned short)(lo >> 16);
                    }
                }
            }
        } else if (t_sel == 0) {
            // Q: single fp16, scaled by 1/8
            #pragma unroll
            for (int mt = 0; mt < 2; mt++) {
                #pragma unroll
                for (int rh = 0; rh < 2; rh++) {
                    const int m = m0 + wm * 32 + mt * 16 + g + rh * 8;
                    const int b = m >> 8, t = m & 255;
                    const size_t base = ((size_t)(b * HH + h) * TT + t) * HS;
                    #pragma unroll
                    for (int nt = 0; nt < 8; nt++) {
                        const int d = nt * 8 + tg * 2;
                        *(uint32_t*)(g_q16 + base + d) =
                            hpack2(acc[mt][nt][rh * 2] * 0.125f, acc[mt][nt][rh * 2 + 1] * 0.125f);
                    }
                }
            }
        } else {
            // K: fp16 hi/lo
            #pragma unroll
            for (int mt = 0; mt < 2; mt++) {
                #pragma unroll
                for (int rh = 0; rh < 2; rh++) {
                    const int m = m0 + wm * 32 + mt * 16 + g + rh * 8;
                    const int b = m >> 8, t = m & 255;
                    const size_t base = ((size_t)(b * HH + h) * TT + t) * HS;
                    #pragma unroll
                    for (int nt = 0; nt < 8; nt++) {
                        const int d = nt * 8 + tg * 2;
                        uint32_t hi, lo;
                        hsplit2(acc[mt][nt][rh * 2], acc[mt][nt][rh * 2 + 1], hi, lo);
                        *(uint32_t*)(g_kh + base + d) = hi;
                        *(uint32_t*)(g_kl + base + d) = lo;
                    }
                }
            }
        }
    } else {
        #pragma unroll
        for (int mt = 0; mt < 2; mt++) {
            #pragma unroll
            for (int rh = 0; rh < 2; rh++) {
                const int m = m0 + wm * 32 + mt * 16 + g + rh * 8;
                #pragma unroll
                for (int nt = 0; nt < 8; nt++) {
                    const int n = n0 + wn * 64 + nt * 8 + tg * 2;
                    float2 v = {acc[mt][nt][rh * 2] + bp[n], acc[mt][nt][rh * 2 + 1] + bp[n + 1]};
                    *(float2*)(out + (size_t)m * CC + n) = v;
                }
            }
        }
    }
}

// ---------------------------------------------------------------------------
// Attention: flash-2 mma.sync, fp16 2-term (Q/P single, K/V split).
// Block = (b,h,half): 128 q rows, 8 warps x 16 rows. K/V chunks of 64 keys.
// smem = 2 regions of 36864B (KH,KL,VH,VL @ 9216 each). Region0 holds Q
// (18432B single fp16) during the prologue only. ONE sync per chunk.
// Total 73728 -> 2 CTAs/SM.
// ---------------------------------------------------------------------------
#define ATT_SMEM 73728
#define SK_H 0
#define SK_L 9216
#define SV_H 18432
#define SV_L 27648

__global__ __launch_bounds__(256, 2) void attn_kernel()
{
    extern __shared__ char sm[];
    const uint32_t sb = smem_u32(sm);

    const int bid = blockIdx.x;
    const int bh = bid >> 1, half = bid & 1;
    const int b = bh / HH, h = bh % HH;
    const int qbase = half * 128;

    const int tid  = threadIdx.x;
    const int lane = tid & 31;
    const int warp = tid >> 5;
    const int g = lane >> 2, tg = lane & 3;

    const int nch = (half == 0) ? 2 : 4;
    const int wmax = qbase + warp * 16 + 15;

    const int srow = tid >> 3;          // 0..31
    const int sseg = (tid & 7) * 8;     // halves

    // stage c: region1 (offset 36864) for even c, region0 (offset 0) for odd c
    auto stage = [&](int c) {
        const uint32_t base = sb + ((c & 1) ? 0u : 36864u);
        const int j0 = c * 64;
        const size_t krow0 = (size_t)bh * TT + j0;
        const size_t vrow0 = (size_t)bh * 64;
        #pragma unroll
        for (int r = 0; r < 2; r++) {
            const int row = srow + r * 32;
            const uint32_t so = (uint32_t)(row * 72 + sseg) * 2;
            CP16(base + SK_H + so, g_kh + (krow0 + row) * HS + sseg);
            CP16(base + SK_L + so, g_kl + (krow0 + row) * HS + sseg);
            CP16(base + SV_H + so, g_vh + (vrow0 + row) * 256 + j0 + sseg);
            CP16(base + SV_L + so, g_vl + (vrow0 + row) * 256 + j0 + sseg);
        }
    };

    // ---- stage Q (single fp16, pre-scaled) into region0
    {
        const size_t qrow0 = (size_t)bh * TT + qbase;
        #pragma unroll
        for (int r = 0; r < 4; r++) {
            const int idx = r * 256 + tid;
            const int row = idx >> 3, seg = (idx & 7) * 8;
            const uint32_t so = (uint32_t)(row * 72 + seg) * 2;
            CP16(sb + so, g_q16 + (qrow0 + row) * HS + seg);
        }
        CP_COMMIT();
    }
    stage(0);                 // region1
    CP_COMMIT();
    CP_WAIT(1);               // Q resident; stage0 may still be in flight
    __syncthreads();

    uint32_t qh[4][4];
    #pragma unroll
    for (int kt = 0; kt < 4; kt++) {
        const int row = warp * 16 + (lane & 15);
        const int col = kt * 16 + (lane >> 4) * 8;
        const uint32_t off = (uint32_t)(row * 72 + col) * 2;
        ldmx4(qh[kt], sb + off);
    }
    // NOTE: no extra sync here — the first loop iteration's top sync orders
    // all warps' Q-fragment reads before stage(1) overwrites region0.

    float o[8][4];
    #pragma unroll
    for (int i = 0; i < 8; i++)
        #pragma unroll
        for (int e = 0; e < 4; e++) o[i][e] = 0.f;
    float m0r = -1e30f, m1r = -1e30f, l0s = 0.f, l1s = 0.f;

    for (int c = 0; c < nch; c++) {
        const int j0 = c * 64;
        CP_WAIT(0);           // stage c complete
        __syncthreads();      // all warps: Q frags read (c=0) / prior compute done
        if (c + 1 < nch) { stage(c + 1); CP_COMMIT(); }

        if (j0 <= wmax) {
            const uint32_t stg = sb + ((c & 1) ? 0u : 36864u);

            // ---- S = Q K^T  (Q single, K 2-term)
            float s[8][4];
            #pragma unroll
            for (int i = 0; i < 8; i++)
                #pragma unroll
                for (int e = 0; e < 4; e++) s[i][e] = 0.f;

            #pragma unroll
            for (int nt = 0; nt < 8; nt++) {
                const int nrow = nt * 8 + (lane & 7);
                #pragma unroll
                for (int kp = 0; kp < 2; kp++) {
                    const int col = kp * 32 + ((lane >> 3) & 3) * 8;
                    const uint32_t off = (uint32_t)(nrow * 72 + col) * 2;
                    uint32_t kh4[4], kl4[4];
                    ldmx4(kh4, stg + SK_H + off);
                    ldmx4(kl4, stg + SK_L + off);
                    mma16816(s[nt], qh[2 * kp],     &kh4[0]);
                    mma16816(s[nt], qh[2 * kp],     &kl4[0]);
                    mma16816(s[nt], qh[2 * kp + 1], &kh4[2]);
                    mma16816(s[nt], qh[2 * kp + 1], &kl4[2]);
                }
            }

            // ---- causal mask
            const int row0 = qbase + warp * 16 + g;
            const int row1 = row0 + 8;
            #pragma unroll
            for (int nt = 0; nt < 8; nt++) {
                #pragma unroll
                for (int e = 0; e < 2; e++) {
                    const int key = j0 + nt * 8 + tg * 2 + e;
                    if (key > row0) s[nt][e] = -1e30f;
                    if (key > row1) s[nt][2 + e] = -1e30f;
                }
            }

            // ---- online softmax
            float vm0 = -1e30f, vm1 = -1e30f;
            #pragma unroll
            for (int nt = 0; nt < 8; nt++) {
                vm0 = fmaxf(vm0, fmaxf(s[nt][0], s[nt][1]));
                vm1 = fmaxf(vm1, fmaxf(s[nt][2], s[nt][3]));
            }
            vm0 = fmaxf(vm0, __shfl_xor_sync(0xffffffffu, vm0, 1));
            vm0 = fmaxf(vm0, __shfl_xor_sync(0xffffffffu, vm0, 2));
            vm1 = fmaxf(vm1, __shfl_xor_sync(0xffffffffu, vm1, 1));
            vm1 = fmaxf(vm1, __shfl_xor_sync(0xffffffffu, vm1, 2));

            const float nm0 = fmaxf(m0r, vm0), nm1 = fmaxf(m1r, vm1);
            const float corr0 = __expf(m0r - nm0), corr1 = __expf(m1r - nm1);
            m0r = nm0; m1r = nm1;

            float ps0 = 0.f, ps1 = 0.f;
            #pragma unroll
            for (int nt = 0; nt < 8; nt++) {
                s[nt][0] = __expf(s[nt][0] - nm0);
                s[nt][1] = __expf(s[nt][1] - nm0);
                s[nt][2] = __expf(s[nt][2] - nm1);
                s[nt][3] = __expf(s[nt][3] - nm1);
                ps0 += s[nt][0] + s[nt][1];
                ps1 += s[nt][2] + s[nt][3];
            }
            ps0 += __shfl_xor_sync(0xffffffffu, ps0, 1);
            ps0 += __shfl_xor_sync(0xffffffffu, ps0, 2);
            ps1 += __shfl_xor_sync(0xffffffffu, ps1, 1);
            ps1 += __shfl_xor_sync(0xffffffffu, ps1, 2);
            l0s = l0s * corr0 + ps0;
            l1s = l1s * corr1 + ps1;
            #pragma unroll
            for (int nt = 0; nt < 8; nt++) {
                o[nt][0] *= corr0; o[nt][1] *= corr0;
                o[nt][2] *= corr1; o[nt][3] *= corr1;
            }

            // ---- O += P V  (P single fp16, V 2-term), by key-half
            #pragma unroll
            for (int kp = 0; kp < 2; kp++) {
                uint32_t ph[2][4];
                #pragma unroll
                for (int kt = 0; kt < 2; kt++) {
                    const int s0 = 4 * kp + 2 * kt;
                    ph[kt][0] = hpack2(s[s0][0],     s[s0][1]);
                    ph[kt][1] = hpack2(s[s0][2],     s[s0][3]);
                    ph[kt][2] = hpack2(s[s0 + 1][0], s[s0 + 1][1]);
                    ph[kt][3] = hpack2(s[s0 + 1][2], s[s0 + 1][3]);
                }
                #pragma unroll
                for (int nt = 0; nt < 8; nt++) {
                    const int nrow = nt * 8 + (lane & 7);
                    const int col = kp * 32 + ((lane >> 3) & 3) * 8;
                    const uint32_t off = (uint32_t)(nrow * 72 + col) * 2;
                    uint32_t vh4[4], vl4[4];
                    ldmx4(vh4, stg + SV_H + off);
                    ldmx4(vl4, stg + SV_L + off);
                    mma16816(o[nt], ph[0], &vh4[0]);
                    mma16816(o[nt], ph[0], &vl4[0]);
                    mma16816(o[nt], ph[1], &vh4[2]);
                    mma16816(o[nt], ph[1], &vl4[2]);
                }
            }
        }
    }

    // ---- write O as single fp16 into g_a16 [m][384]
    const float inv0 = 1.f / l0s, inv1 = 1.f / l1s;
    const int row0 = qbase + warp * 16 + g;
    const int row1 = row0 + 8;
    #pragma unroll
    for (int nt = 0; nt < 8; nt++) {
        const int col = h * 64 + nt * 8 + tg * 2;
        const size_t i0 = (size_t)(b * TT + row0) * CC + col;
        const size_t i1 = (size_t)(b * TT + row1) * CC + col;
        *(uint32_t*)(g_a16 + i0) = hpack2(o[nt][0] * inv0, o[nt][1] * inv0);
        *(uint32_t*)(g_a16 + i1) = hpack2(o[nt][2] * inv1, o[nt][3] * inv1);
    }
}

// ---------------------------------------------------------------------------
extern "C" void kernel_launch(void* const* d_in, const int* in_sizes, int n_in,
                              void* d_out, int out_size)
{
    const float* x  = (const float*)d_in[0];
    const float* Wq = (const float*)d_in[1];
    const float* Wk = (const float*)d_in[2];
    const float* Wv = (const float*)d_in[3];
    const float* Wp = (const float*)d_in[4];
    const float* bp = (const float*)d_in[5];
    float* out = (float*)d_out;

    cudaFuncSetAttribute(gemm_kernel<0>, cudaFuncAttributeMaxDynamicSharedMemorySize, GEMM_SMEM);
    cudaFuncSetAttribute(gemm_kernel<1>, cudaFuncAttributeMaxDynamicSharedMemorySize, GEMM_SMEM);
    cudaFuncSetAttribute(attn_kernel,    cudaFuncAttributeMaxDynamicSharedMemorySize, ATT_SMEM);

    conv_all<<<CONV_XBLK + CONV_WBLK, 256>>>(x, Wq, Wk, Wv, Wp);

    __half *x16, *wh, *wl, *a16;
    cudaGetSymbolAddress((void**)&x16, g_x16);
    cudaGetSymbolAddress((void**)&wh,  g_wh);
    cudaGetSymbolAddress((void**)&wl,  g_wl);
    cudaGetSymbolAddress((void**)&a16, g_a16);

    dim3 g1(MTOT / 128, 9);
    gemm_kernel<0><<<g1, 256, GEMM_SMEM>>>(x16, wh, wl, nullptr, nullptr);

    attn_kernel<<<BB * HH * 2, 256, ATT_SMEM>>>();

    dim3 g3(MTOT / 128, 3);
    gemm_kernel<1><<<g3, 256, GEMM_SMEM>>>(a16, wh + 1152 * 384, wl + 1152 * 384, bp, out);
}

// round 17
// speedup vs baseline: 5.9309x; 1.1716x over previous
#include <cuda_runtime.h>
#include <cuda_fp16.h>
#include <cstdint>

#define BB   128
#define TT   256
#define CC   384
#define HH   6
#define HS   64
#define MTOT (BB*TT)
#define QKV_E 12582912     // = MTOT*CC = BB*HH*TT*HS

// ---------------------------------------------------------------------------
// fp16 scratch (allocation-free rule: __device__ globals)
// Activations: single fp16. Stationary operands: fp16 hi + lo.
// ---------------------------------------------------------------------------
__device__ __half g_x16[QKV_E];                      // x        [m][384]
__device__ __half g_q16[QKV_E];                      // q*0.125  [bh][t][64]
__device__ __half g_kh[QKV_E], g_kl[QKV_E];          // k        [bh][t][64]
__device__ __half g_vh[QKV_E], g_vl[QKV_E];          // V^T      [bh][d][256]
__device__ __half g_a16[QKV_E];                      // attn out [m][384]
__device__ __half g_wh[1536*384], g_wl[1536*384];    // Wall(1152)+Wpt(384), [n][k]

// ---------------------------------------------------------------------------
// helpers
// ---------------------------------------------------------------------------
__device__ __forceinline__ uint32_t smem_u32(const void* p) {
    uint32_t a;
    asm("{ .reg .u64 t; cvta.to.shared.u64 t, %1; cvt.u32.u64 %0, t; }" : "=r"(a) : "l"(p));
    return a;
}
__device__ __forceinline__ void mma16816(float* c, const uint32_t* a, const uint32_t* b) {
    asm volatile(
        "mma.sync.aligned.m16n8k16.row.col.f32.f16.f16.f32 "
        "{%0,%1,%2,%3}, {%4,%5,%6,%7}, {%8,%9}, {%0,%1,%2,%3};"
        : "+f"(c[0]), "+f"(c[1]), "+f"(c[2]), "+f"(c[3])
        : "r"(a[0]), "r"(a[1]), "r"(a[2]), "r"(a[3]), "r"(b[0]), "r"(b[1]));
}
__device__ __forceinline__ void ldmx4(uint32_t* r, uint32_t addr) {
    asm volatile("ldmatrix.sync.aligned.m8n8.x4.shared.b16 {%0,%1,%2,%3}, [%4];"
        : "=r"(r[0]), "=r"(r[1]), "=r"(r[2]), "=r"(r[3]) : "r"(addr));
}
#define CP16(dst, src) asm volatile("cp.async.ca.shared.global [%0], [%1], 16;" :: "r"(dst), "l"(src))
#define CP_COMMIT()    asm volatile("cp.async.commit_group;")
#define CP_WAIT(n)     asm volatile("cp.async.wait_group %0;" :: "n"(n))

__device__ __forceinline__ uint32_t hpack2(float a, float b) {
    __half2 h = __floats2half2_rn(a, b);      // a -> low half
    return reinterpret_cast<uint32_t&>(h);
}
__device__ __forceinline__ void hsplit2(float a, float b, uint32_t& hi, uint32_t& lo) {
    const float ha = __half2float(__float2half_rn(a));
    const float hb = __half2float(__float2half_rn(b));
    hi = hpack2(ha, hb);
    lo = hpack2(a - ha, b - hb);
}
__device__ __forceinline__ void hsplit1(float a, __half& h, __half& l) {
    h = __float2half_rn(a);
    l = __float2half_rn(a - __half2float(h));
}

// ---------------------------------------------------------------------------
// merged convert kernel (one-shot, bandwidth-bound)
// blocks [0, 12288): x -> fp16.  blocks [12288, 14592): weights -> fp16 hi/lo
// ---------------------------------------------------------------------------
#define CONV_XBLK 12288
#define CONV_WBLK 2304

__global__ __launch_bounds__(256) void conv_all(
    const float* __restrict__ x,
    const float* __restrict__ Wq, const float* __restrict__ Wk,
    const float* __restrict__ Wv, const float* __restrict__ Wp)
{
    if (blockIdx.x < CONV_XBLK) {
        const int i = blockIdx.x * 256 + threadIdx.x;     // per float4
        float4 v = ((const float4*)x)[i];
        uint2 p;
        p.x = hpack2(v.x, v.y);
        p.y = hpack2(v.z, v.w);
        ((uint2*)g_x16)[i] = p;
    } else {
        const int i = (blockIdx.x - CONV_XBLK) * 256 + threadIdx.x;   // 1536*384
        const int row = i / 384, k = i % 384;
        float val;
        if (row < 1152) {
            const int t = row / 384, rem = row % 384, h = rem / 64, d = rem % 64;
            const float* W = (t == 0 ? Wq : t == 1 ? Wk : Wv);
            val = W[((size_t)h * 384 + k) * 64 + d];
        } else {
            const int n = row - 1152;
            val = Wp[(size_t)k * 384 + n];
        }
        __half hh, ll;
        hsplit1(val, hh, ll);
        g_wh[i] = hh;
        g_wl[i] = ll;
    }
}

// ---------------------------------------------------------------------------
// GEMM: C[128,128] tiles. A single fp16 [m][384]; B split fp16 [n][384].
// 128 threads, 4 warps in 2x2; each warp owns a 64x64 tile (smem-traffic
// minimal layout). 3-stage cp.async rotation, one __syncthreads per chunk.
// stage: A 0 (10240B), BH 10240, BL 20480 -> 30720B; 3 stages = 92160
// ---------------------------------------------------------------------------
#define GEMM_SMEM 92160

template <int MODE>
__global__ __launch_bounds__(128, 2) void gemm_kernel(
    const __half* __restrict__ A16,
    const __half* __restrict__ Bh, const __half* __restrict__ Bl,
    const float* __restrict__ bp, float* __restrict__ out)
{
    extern __shared__ char sm[];
    const uint32_t sb = smem_u32(sm);

    const int tid  = threadIdx.x;          // 0..127
    const int lane = tid & 31;
    const int warp = tid >> 5;             // 0..3
    const int wm = warp & 1;               // 64-row group
    const int wn = warp >> 1;              // 64-col group

    const int m0 = blockIdx.x * 128;
    const int n0 = blockIdx.y * 128;

    const int rowL = tid >> 2;             // 0..31
    const int segL = (tid & 3) * 8;        // halves (16B)
    const uint32_t soBase = (uint32_t)(rowL * 40 + segL) * 2;

    float acc[4][8][4];
    #pragma unroll
    for (int i = 0; i < 4; i++)
        #pragma unroll
        for (int j = 0; j < 8; j++)
            #pragma unroll
            for (int e = 0; e < 4; e++) acc[i][j][e] = 0.f;

    auto issue = [&](int ch, int s) {
        const uint32_t base = sb + s * 30720;
        const int kof = ch * 32 + segL;
        #pragma unroll
        for (int r = 0; r < 4; r++) {
            const int row = rowL + r * 32;
            const uint32_t so = soBase + r * 32 * 80;
            CP16(base +         so, A16 + (size_t)(m0 + row) * 384 + kof);
            CP16(base + 10240 + so, Bh  + (size_t)(n0 + row) * 384 + kof);
            CP16(base + 20480 + so, Bl  + (size_t)(n0 + row) * 384 + kof);
        }
    };

    issue(0, 0); CP_COMMIT();
    issue(1, 1); CP_COMMIT();

    int sc = 0;                 // ch % 3
    int si = 2;                 // (ch+2) % 3
    for (int ch = 0; ch < 12; ch++) {
        if (ch < 11) { CP_WAIT(1); }      // load ch complete (ch+1 may be pending)
        else         { CP_WAIT(0); }
        __syncthreads();                  // also retires reads of buffer si (iter ch-1)
        if (ch + 2 < 12) { issue(ch + 2, si); CP_COMMIT(); }

        const uint32_t sbuf = sb + sc * 30720;

        // hoist A fragments for this chunk: [k16][mt]
        uint32_t ah[2][4][4];
        #pragma unroll
        for (int k16 = 0; k16 < 2; k16++) {
            #pragma unroll
            for (int mt = 0; mt < 4; mt++) {
                const int row = wm * 64 + mt * 16 + (lane & 15);
                const int col = k16 * 16 + (lane >> 4) * 8;
                const uint32_t off = (uint32_t)(row * 40 + col) * 2;
                ldmx4(ah[k16][mt], sbuf + off);
            }
        }

        #pragma unroll
        for (int nt = 0; nt < 8; nt++) {
            const int nrow = wn * 64 + nt * 8 + (lane & 7);
            const int col = ((lane >> 3) & 3) * 8;          // covers both k16
            const uint32_t off = (uint32_t)(nrow * 40 + col) * 2;
            uint32_t bh4[4], bl4[4];
            ldmx4(bh4, sbuf + 10240 + off);
            ldmx4(bl4, sbuf + 20480 + off);
            #pragma unroll
            for (int k16 = 0; k16 < 2; k16++) {
                #pragma unroll
                for (int mt = 0; mt < 4; mt++) {
                    mma16816(acc[mt][nt], ah[k16][mt], &bh4[2 * k16]);
                    mma16816(acc[mt][nt], ah[k16][mt], &bl4[2 * k16]);
                }
            }
        }
        sc = (sc == 2) ? 0 : sc + 1;
        si = (si == 2) ? 0 : si + 1;
    }

    // ---- epilogue
    const int g = lane >> 2, tg = lane & 3;
    if (MODE == 0) {
        const int t_sel = (blockIdx.y * 128) / 384;
        const int h = ((blockIdx.y * 128) % 384) / 64 + wn;
        if (t_sel == 2) {
            // V: write TRANSPOSED [bh][d][256] fp16 hi/lo
            unsigned short* dh = (unsigned short*)g_vh;
            unsigned short* dl = (unsigned short*)g_vl;
            #pragma unroll
            for (int mt = 0; mt < 4; mt++) {
                #pragma unroll
                for (int rh = 0; rh < 2; rh++) {
                    const int m = m0 + wm * 64 + mt * 16 + g + rh * 8;
                    const int b = m >> 8, t = m & 255;
                    const size_t bhb = (size_t)(b * HH + h) * 64;
                    #pragma unroll
                    for (int nt = 0; nt < 8; nt++) {
                        const int d = nt * 8 + tg * 2;
                        uint32_t hi, lo;
                        hsplit2(acc[mt][nt][rh * 2], acc[mt][nt][rh * 2 + 1], hi, lo);
                        const size_t base = (bhb + d) * 256 + t;
                        dh[base] = (unsigned short)(hi & 0xffff);
                        dh[base + 256] = (unsigned short)(hi >> 16);
                        dl[base] = (unsigned short)(lo & 0xffff);
                        dl[base + 256] = (unsigned short)(lo >> 16);
                    }
                }
            }
        } else if (t_sel == 0) {
            // Q: single fp16, scaled by 1/8
            #pragma unroll
            for (int mt = 0; mt < 4; mt++) {
                #pragma unroll
                for (int rh = 0; rh < 2; rh++) {
                    const int m = m0 + wm * 64 + mt * 16 + g + rh * 8;
                    const int b = m >> 8, t = m & 255;
                    const size_t base = ((size_t)(b * HH + h) * TT + t) * HS;
                    #pragma unroll
                    for (int nt = 0; nt < 8; nt++) {
                        const int d = nt * 8 + tg * 2;
                        *(uint32_t*)(g_q16 + base + d) =
                            hpack2(acc[mt][nt][rh * 2] * 0.125f, acc[mt][nt][rh * 2 + 1] * 0.125f);
                    }
                }
            }
        } else {
            // K: fp16 hi/lo
            #pragma unroll
            for (int mt = 0; mt < 4; mt++) {
                #pragma unroll
                for (int rh = 0; rh < 2; rh++) {
                    const int m = m0 + wm * 64 + mt * 16 + g + rh * 8;
                    const int b = m >> 8, t = m & 255;
                    const size_t base = ((size_t)(b * HH + h) * TT + t) * HS;
                    #pragma unroll
                    for (int nt = 0; nt < 8; nt++) {
                        const int d = nt * 8 + tg * 2;
                        uint32_t hi, lo;
                        hsplit2(acc[mt][nt][rh * 2], acc[mt][nt][rh * 2 + 1], hi, lo);
                        *(uint32_t*)(g_kh + base + d) = hi;
                        *(uint32_t*)(g_kl + base + d) = lo;
                    }
                }
            }
        }
    } else {
        #pragma unroll
        for (int mt = 0; mt < 4; mt++) {
            #pragma unroll
            for (int rh = 0; rh < 2; rh++) {
                const int m = m0 + wm * 64 + mt * 16 + g + rh * 8;
                #pragma unroll
                for (int nt = 0; nt < 8; nt++) {
                    const int n = n0 + wn * 64 + nt * 8 + tg * 2;
                    float2 v = {acc[mt][nt][rh * 2] + bp[n], acc[mt][nt][rh * 2 + 1] + bp[n + 1]};
                    *(float2*)(out + (size_t)m * CC + n) = v;
                }
            }
        }
    }
}

// ---------------------------------------------------------------------------
// Attention: flash-2 mma.sync, fp16 2-term (Q/P single, K/V split).
// Block = (b,h,half): 128 q rows, 8 warps x 16 rows. K/V chunks of 64 keys.
// smem = 2 regions of 36864B (KH,KL,VH,VL @ 9216 each). Region0 holds Q
// (18432B single fp16) during the prologue only. ONE sync per chunk.
// Total 73728 -> 2 CTAs/SM.
// ---------------------------------------------------------------------------
#define ATT_SMEM 73728
#define SK_H 0
#define SK_L 9216
#define SV_H 18432
#define SV_L 27648

__global__ __launch_bounds__(256, 2) void attn_kernel()
{
    extern __shared__ char sm[];
    const uint32_t sb = smem_u32(sm);

    const int bid = blockIdx.x;
    const int bh = bid >> 1, half = bid & 1;
    const int b = bh / HH, h = bh % HH;
    const int qbase = half * 128;

    const int tid  = threadIdx.x;
    const int lane = tid & 31;
    const int warp = tid >> 5;
    const int g = lane >> 2, tg = lane & 3;

    const int nch = (half == 0) ? 2 : 4;
    const int wmax = qbase + warp * 16 + 15;

    const int srow = tid >> 3;          // 0..31
    const int sseg = (tid & 7) * 8;     // halves

    // stage c: region1 (offset 36864) for even c, region0 (offset 0) for odd c
    auto stage = [&](int c) {
        const uint32_t base = sb + ((c & 1) ? 0u : 36864u);
        const int j0 = c * 64;
        const size_t krow0 = (size_t)bh * TT + j0;
        const size_t vrow0 = (size_t)bh * 64;
        #pragma unroll
        for (int r = 0; r < 2; r++) {
            const int row = srow + r * 32;
            const uint32_t so = (uint32_t)(row * 72 + sseg) * 2;
            CP16(base + SK_H + so, g_kh + (krow0 + row) * HS + sseg);
            CP16(base + SK_L + so, g_kl + (krow0 + row) * HS + sseg);
            CP16(base + SV_H + so, g_vh + (vrow0 + row) * 256 + j0 + sseg);
            CP16(base + SV_L + so, g_vl + (vrow0 + row) * 256 + j0 + sseg);
        }
    };

    // ---- stage Q (single fp16, pre-scaled) into region0
    {
        const size_t qrow0 = (size_t)bh * TT + qbase;
        #pragma unroll
        for (int r = 0; r < 4; r++) {
            const int idx = r * 256 + tid;
            const int row = idx >> 3, seg = (idx & 7) * 8;
            const uint32_t so = (uint32_t)(row * 72 + seg) * 2;
            CP16(sb + so, g_q16 + (qrow0 + row) * HS + seg);
        }
        CP_COMMIT();
    }
    stage(0);                 // region1
    CP_COMMIT();
    CP_WAIT(1);               // Q resident; stage0 may still be in flight
    __syncthreads();

    uint32_t qh[4][4];
    #pragma unroll
    for (int kt = 0; kt < 4; kt++) {
        const int row = warp * 16 + (lane & 15);
        const int col = kt * 16 + (lane >> 4) * 8;
        const uint32_t off = (uint32_t)(row * 72 + col) * 2;
        ldmx4(qh[kt], sb + off);
    }
    // NOTE: no extra sync here — the first loop iteration's top sync orders
    // all warps' Q-fragment reads before stage(1) overwrites region0.

    float o[8][4];
    #pragma unroll
    for (int i = 0; i < 8; i++)
        #pragma unroll
        for (int e = 0; e < 4; e++) o[i][e] = 0.f;
    float m0r = -1e30f, m1r = -1e30f, l0s = 0.f, l1s = 0.f;

    for (int c = 0; c < nch; c++) {
        const int j0 = c * 64;
        CP_WAIT(0);           // stage c complete
        __syncthreads();      // all warps: Q frags read (c=0) / prior compute done
        if (c + 1 < nch) { stage(c + 1); CP_COMMIT(); }

        if (j0 <= wmax) {
            const uint32_t stg = sb + ((c & 1) ? 0u : 36864u);

            // ---- S = Q K^T  (Q single, K 2-term)
            float s[8][4];
            #pragma unroll
            for (int i = 0; i < 8; i++)
                #pragma unroll
                for (int e = 0; e < 4; e++) s[i][e] = 0.f;

            #pragma unroll
            for (int nt = 0; nt < 8; nt++) {
                const int nrow = nt * 8 + (lane & 7);
                #pragma unroll
                for (int kp = 0; kp < 2; kp++) {
                    const int col = kp * 32 + ((lane >> 3) & 3) * 8;
                    const uint32_t off = (uint32_t)(nrow * 72 + col) * 2;
                    uint32_t kh4[4], kl4[4];
                    ldmx4(kh4, stg + SK_H + off);
                    ldmx4(kl4, stg + SK_L + off);
                    mma16816(s[nt], qh[2 * kp],     &kh4[0]);
                    mma16816(s[nt], qh[2 * kp],     &kl4[0]);
                    mma16816(s[nt], qh[2 * kp + 1], &kh4[2]);
                    mma16816(s[nt], qh[2 * kp + 1], &kl4[2]);
                }
            }

            // ---- causal mask
            const int row0 = qbase + warp * 16 + g;
            const int row1 = row0 + 8;
            #pragma unroll
            for (int nt = 0; nt < 8; nt++) {
                #pragma unroll
                for (int e = 0; e < 2; e++) {
                    const int key = j0 + nt * 8 + tg * 2 + e;
                    if (key > row0) s[nt][e] = -1e30f;
                    if (key > row1) s[nt][2 + e] = -1e30f;
                }
            }

            // ---- online softmax
            float vm0 = -1e30f, vm1 = -1e30f;
            #pragma unroll
            for (int nt = 0; nt < 8; nt++) {
                vm0 = fmaxf(vm0, fmaxf(s[nt][0], s[nt][1]));
                vm1 = fmaxf(vm1, fmaxf(s[nt][2], s[nt][3]));
            }
            vm0 = fmaxf(vm0, __shfl_xor_sync(0xffffffffu, vm0, 1));
            vm0 = fmaxf(vm0, __shfl_xor_sync(0xffffffffu, vm0, 2));
            vm1 = fmaxf(vm1, __shfl_xor_sync(0xffffffffu, vm1, 1));
            vm1 = fmaxf(vm1, __shfl_xor_sync(0xffffffffu, vm1, 2));

            const float nm0 = fmaxf(m0r, vm0), nm1 = fmaxf(m1r, vm1);
            const float corr0 = __expf(m0r - nm0), corr1 = __expf(m1r - nm1);
            m0r = nm0; m1r = nm1;

            float ps0 = 0.f, ps1 = 0.f;
            #pragma unroll
            for (int nt = 0; nt < 8; nt++) {
                s[nt][0] = __expf(s[nt][0] - nm0);
                s[nt][1] = __expf(s[nt][1] - nm0);
                s[nt][2] = __expf(s[nt][2] - nm1);
                s[nt][3] = __expf(s[nt][3] - nm1);
                ps0 += s[nt][0] + s[nt][1];
                ps1 += s[nt][2] + s[nt][3];
            }
            ps0 += __shfl_xor_sync(0xffffffffu, ps0, 1);
            ps0 += __shfl_xor_sync(0xffffffffu, ps0, 2);
            ps1 += __shfl_xor_sync(0xffffffffu, ps1, 1);
            ps1 += __shfl_xor_sync(0xffffffffu, ps1, 2);
            l0s = l0s * corr0 + ps0;
            l1s = l1s * corr1 + ps1;
            #pragma unroll
            for (int nt = 0; nt < 8; nt++) {
                o[nt][0] *= corr0; o[nt][1] *= corr0;
                o[nt][2] *= corr1; o[nt][3] *= corr1;
            }

            // ---- O += P V  (P single fp16, V 2-term), by key-half
            #pragma unroll
            for (int kp = 0; kp < 2; kp++) {
                uint32_t ph[2][4];
                #pragma unroll
                for (int kt = 0; kt < 2; kt++) {
                    const int s0 = 4 * kp + 2 * kt;
                    ph[kt][0] = hpack2(s[s0][0],     s[s0][1]);
                    ph[kt][1] = hpack2(s[s0][2],     s[s0][3]);
                    ph[kt][2] = hpack2(s[s0 + 1][0], s[s0 + 1][1]);
                    ph[kt][3] = hpack2(s[s0 + 1][2], s[s0 + 1][3]);
                }
                #pragma unroll
                for (int nt = 0; nt < 8; nt++) {
                    const int nrow = nt * 8 + (lane & 7);
                    const int col = kp * 32 + ((lane >> 3) & 3) * 8;
                    const uint32_t off = (uint32_t)(nrow * 72 + col) * 2;
                    uint32_t vh4[4], vl4[4];
                    ldmx4(vh4, stg + SV_H + off);
                    ldmx4(vl4, stg + SV_L + off);
                    mma16816(o[nt], ph[0], &vh4[0]);
                    mma16816(o[nt], ph[0], &vl4[0]);
                    mma16816(o[nt], ph[1], &vh4[2]);
                    mma16816(o[nt], ph[1], &vl4[2]);
                }
            }
        }
    }

    // ---- write O as single fp16 into g_a16 [m][384]
    const float inv0 = 1.f / l0s, inv1 = 1.f / l1s;
    const int row0 = qbase + warp * 16 + g;
    const int row1 = row0 + 8;
    #pragma unroll
    for (int nt = 0; nt < 8; nt++) {
        const int col = h * 64 + nt * 8 + tg * 2;
        const size_t i0 = (size_t)(b * TT + row0) * CC + col;
        const size_t i1 = (size_t)(b * TT + row1) * CC + col;
        *(uint32_t*)(g_a16 + i0) = hpack2(o[nt][0] * inv0, o[nt][1] * inv0);
        *(uint32_t*)(g_a16 + i1) = hpack2(o[nt][2] * inv1, o[nt][3] * inv1);
    }
}

// ---------------------------------------------------------------------------
extern "C" void kernel_launch(void* const* d_in, const int* in_sizes, int n_in,
                              void* d_out, int out_size)
{
    const float* x  = (const float*)d_in[0];
    const float* Wq = (const float*)d_in[1];
    const float* Wk = (const float*)d_in[2];
    const float* Wv = (const float*)d_in[3];
    const float* Wp = (const float*)d_in[4];
    const float* bp = (const float*)d_in[5];
    float* out = (float*)d_out;

    cudaFuncSetAttribute(gemm_kernel<0>, cudaFuncAttributeMaxDynamicSharedMemorySize, GEMM_SMEM);
    cudaFuncSetAttribute(gemm_kernel<1>, cudaFuncAttributeMaxDynamicSharedMemorySize, GEMM_SMEM);
    cudaFuncSetAttribute(attn_kernel,    cudaFuncAttributeMaxDynamicSharedMemorySize, ATT_SMEM);

    conv_all<<<CONV_XBLK + CONV_WBLK, 256>>>(x, Wq, Wk, Wv, Wp);

    __half *x16, *wh, *wl, *a16;
    cudaGetSymbolAddress((void**)&x16, g_x16);
    cudaGetSymbolAddress((void**)&wh,  g_wh);
    cudaGetSymbolAddress((void**)&wl,  g_wl);
    cudaGetSymbolAddress((void**)&a16, g_a16);

    dim3 g1(MTOT / 128, 9);
    gemm_kernel<0><<<g1, 128, GEMM_SMEM>>>(x16, wh, wl, nullptr, nullptr);

    attn_kernel<<<BB * HH * 2, 256, ATT_SMEM>>>();

    dim3 g3(MTOT / 128, 3);
    gemm_kernel<1><<<g3, 128, GEMM_SMEM>>>(a16, wh + 1152 * 384, wl + 1152 * 384, bp, out);
}